// round 2
// baseline (speedup 1.0000x reference)
#include <cuda_runtime.h>
#include <cuda_bf16.h>

// Problem constants
#define BB   128
#define TT   256
#define CC   384
#define HH   6
#define DD   64
#define MM   128
#define WIN  64
#define C3   (3*CC)      // 1152
#define ROWS (BB*TT)     // 32768

// Scratch (allocation-free rule: __device__ globals)
__device__ float g_qkv[ROWS * C3];   // [B*T, 3C]
__device__ float g_y[ROWS * CC];     // gated attention output [B*T, C]

// ---------- packed f32x2 helpers ----------
typedef unsigned long long u64;

__device__ __forceinline__ u64 pack2(float lo, float hi) {
    u64 r;
    asm("mov.b64 %0, {%1, %2};" : "=l"(r) : "f"(lo), "f"(hi));
    return r;
}
__device__ __forceinline__ void unpack2(u64 v, float& lo, float& hi) {
    asm("mov.b64 {%0, %1}, %2;" : "=f"(lo), "=f"(hi) : "l"(v));
}
__device__ __forceinline__ void fma2(u64& d, u64 a, u64 b) {
    asm("fma.rn.f32x2 %0, %1, %2, %0;" : "+l"(d) : "l"(a), "l"(b));
}

// ============================================================
// GEMM: C[M,N] = A[M,K] @ B[K,N] + bias[N]
// 64x64 block tile, 256 threads, 4x4 micro-tile, BK=16, f32x2 FMA
// ============================================================
__global__ __launch_bounds__(256) void gemm_bias_kernel(
    const float* __restrict__ A, const float* __restrict__ Bm,
    const float* __restrict__ bias, float* __restrict__ C,
    int N, int K)
{
    __shared__ float As[16][68];   // [k][m]
    __shared__ float Bs[16][68];   // [k][n]

    const int tid = threadIdx.x;
    const int tx = tid & 15, ty = tid >> 4;
    const int n0 = blockIdx.x * 64;
    const int m0 = blockIdx.y * 64;

    u64 acc[4][2] = {};

    for (int k0 = 0; k0 < K; k0 += 16) {
        // Load A tile transposed: As[k][m]
        {
            const int kk = tid & 15;
            const int mb = tid >> 4;
            #pragma unroll
            for (int p = 0; p < 4; ++p)
                As[kk][mb + 16*p] = A[(size_t)(m0 + mb + 16*p) * K + k0 + kk];
        }
        // Load B tile: Bs[k][n]
        {
            const int nn = tid & 63;
            const int kb = tid >> 6;
            #pragma unroll
            for (int p = 0; p < 4; ++p)
                Bs[kb + 4*p][nn] = Bm[(size_t)(k0 + kb + 4*p) * N + n0 + nn];
        }
        __syncthreads();

        #pragma unroll
        for (int kk = 0; kk < 16; ++kk) {
            float4 a4 = *(const float4*)&As[kk][ty*4];
            float4 b4 = *(const float4*)&Bs[kk][tx*4];
            u64 bp0 = pack2(b4.x, b4.y);
            u64 bp1 = pack2(b4.z, b4.w);
            float av[4] = {a4.x, a4.y, a4.z, a4.w};
            #pragma unroll
            for (int i = 0; i < 4; ++i) {
                u64 ad = pack2(av[i], av[i]);
                fma2(acc[i][0], ad, bp0);
                fma2(acc[i][1], ad, bp1);
            }
        }
        __syncthreads();
    }

    // Epilogue
    #pragma unroll
    for (int i = 0; i < 4; ++i) {
        float c0, c1, c2, c3;
        unpack2(acc[i][0], c0, c1);
        unpack2(acc[i][1], c2, c3);
        const int row = m0 + ty*4 + i;
        const int col = n0 + tx*4;
        float* outp = &C[(size_t)row * N + col];
        outp[0] = c0 + bias[col + 0];
        outp[1] = c1 + bias[col + 1];
        outp[2] = c2 + bias[col + 2];
        outp[3] = c3 + bias[col + 3];
    }
}

// ============================================================
// Attention kernel.
// Block = (q-tile of 64, head, batch). 256 threads.
// Keys: slots 0..127 = memory prefix, slots 128..255 = self
// positions [qs-64, qs+63] (superset of the causal+window set).
// Full 64x256 score tile in smem, two-pass softmax, then AV.
// Epilogue applies 1/sum and gate; writes g_y.
// ============================================================
#define QPAD 68
#define SROW 260
#define ATTN_SMEM_FLOATS (64*QPAD + 64*QPAD + 64*SROW + 64)

__global__ __launch_bounds__(256) void attn_kernel(
    const float* __restrict__ qkv, const float* __restrict__ mem,
    const float* __restrict__ gate, float* __restrict__ y)
{
    extern __shared__ float sm[];
    float* Qs   = sm;                       // [64][68]
    float* KVs  = sm + 64*QPAD;             // [64][68]
    float* Ss   = sm + 2*64*QPAD;           // [64][260]
    float* rinv = Ss + 64*SROW;             // [64]

    const int qt = blockIdx.x, h = blockIdx.y, b = blockIdx.z;
    const int qs = qt * 64;
    const int tid = threadIdx.x;
    const int tx = tid & 15, ty = tid >> 4;

    // ---- load Q tile ----
    {
        const int d = tid & 63;
        const int r0 = tid >> 6;
        #pragma unroll
        for (int r = r0; r < 64; r += 4)
            Qs[r*QPAD + d] = qkv[(size_t)(b*TT + qs + r) * C3 + h*DD + d];
    }

    // ---- scores: 4 key chunks of 64 ----
    for (int c = 0; c < 4; ++c) {
        __syncthreads();
        {   // load K chunk into KVs
            const int d = tid & 63;
            const int r0 = tid >> 6;
            #pragma unroll
            for (int r = r0; r < 64; r += 4) {
                float val;
                if (c < 2) {
                    val = mem[(size_t)(c*64 + r) * CC + h*DD + d];
                } else {
                    const int p = qs - 64 + (c - 2)*64 + r;
                    val = (p >= 0) ? qkv[(size_t)(b*TT + p) * C3 + CC + h*DD + d] : 0.f;
                }
                KVs[r*QPAD + d] = val;
            }
        }
        __syncthreads();

        u64 acc[4][2] = {};
        for (int d4 = 0; d4 < DD; d4 += 4) {
            float kv[4][4], qv[4][4];
            #pragma unroll
            for (int j = 0; j < 4; ++j)
                *(float4*)&kv[j][0] = *(const float4*)&KVs[(tx*4 + j)*QPAD + d4];
            #pragma unroll
            for (int i = 0; i < 4; ++i)
                *(float4*)&qv[i][0] = *(const float4*)&Qs[(ty*4 + i)*QPAD + d4];
            #pragma unroll
            for (int dd = 0; dd < 4; ++dd) {
                u64 kp0 = pack2(kv[0][dd], kv[1][dd]);
                u64 kp1 = pack2(kv[2][dd], kv[3][dd]);
                #pragma unroll
                for (int i = 0; i < 4; ++i) {
                    u64 qd = pack2(qv[i][dd], qv[i][dd]);
                    fma2(acc[i][0], qd, kp0);
                    fma2(acc[i][1], qd, kp1);
                }
            }
        }
        // mask + scale + store to Ss
        #pragma unroll
        for (int i = 0; i < 4; ++i) {
            float s[4];
            unpack2(acc[i][0], s[0], s[1]);
            unpack2(acc[i][1], s[2], s[3]);
            const int qi = qs + ty*4 + i;
            #pragma unroll
            for (int j = 0; j < 4; ++j) {
                const int ks = c*64 + tx*4 + j;
                bool valid;
                if (ks < MM) {
                    valid = true;
                } else {
                    const int jj = qs - 64 + (ks - MM);
                    valid = (jj >= 0) && (jj <= qi) && (qi - jj <= WIN);
                }
                Ss[(ty*4 + i)*SROW + ks] = valid ? s[j] * 0.125f : -1e30f;
            }
        }
    }
    __syncthreads();

    // ---- softmax: warp w owns rows w*8..w*8+7 ----
    {
        const int w = tid >> 5, l = tid & 31;
        for (int rr = 0; rr < 8; ++rr) {
            const int r = w*8 + rr;
            float* row = &Ss[r*SROW];
            float mx = -1e30f;
            #pragma unroll
            for (int cidx = l; cidx < 256; cidx += 32)
                mx = fmaxf(mx, row[cidx]);
            #pragma unroll
            for (int off = 16; off > 0; off >>= 1)
                mx = fmaxf(mx, __shfl_xor_sync(0xFFFFFFFFu, mx, off));
            float sum = 0.f;
            #pragma unroll
            for (int cidx = l; cidx < 256; cidx += 32) {
                float e = __expf(row[cidx] - mx);
                row[cidx] = e;
                sum += e;
            }
            #pragma unroll
            for (int off = 16; off > 0; off >>= 1)
                sum += __shfl_xor_sync(0xFFFFFFFFu, sum, off);
            if (l == 0) rinv[r] = 1.0f / sum;
        }
    }

    // ---- AV: out[64 q][64 d] ----
    u64 oacc[4][2] = {};
    for (int c = 0; c < 4; ++c) {
        __syncthreads();
        {   // load V chunk into KVs
            const int d = tid & 63;
            const int r0 = tid >> 6;
            #pragma unroll
            for (int r = r0; r < 64; r += 4) {
                float val;
                if (c < 2) {
                    val = mem[(size_t)(c*64 + r) * CC + h*DD + d];
                } else {
                    const int p = qs - 64 + (c - 2)*64 + r;
                    val = (p >= 0) ? qkv[(size_t)(b*TT + p) * C3 + 2*CC + h*DD + d] : 0.f;
                }
                KVs[r*QPAD + d] = val;
            }
        }
        __syncthreads();

        for (int kk4 = 0; kk4 < 64; kk4 += 4) {
            float pv[4][4], vv[4][4];
            #pragma unroll
            for (int i = 0; i < 4; ++i)
                *(float4*)&pv[i][0] = *(const float4*)&Ss[(ty*4 + i)*SROW + c*64 + kk4];
            #pragma unroll
            for (int r = 0; r < 4; ++r)
                *(float4*)&vv[r][0] = *(const float4*)&KVs[(kk4 + r)*QPAD + tx*4];
            #pragma unroll
            for (int r = 0; r < 4; ++r) {
                u64 vp0 = pack2(vv[r][0], vv[r][1]);
                u64 vp1 = pack2(vv[r][2], vv[r][3]);
                #pragma unroll
                for (int i = 0; i < 4; ++i) {
                    u64 pd = pack2(pv[i][r], pv[i][r]);
                    fma2(oacc[i][0], pd, vp0);
                    fma2(oacc[i][1], pd, vp1);
                }
            }
        }
    }

    // ---- epilogue: normalize, gate, write g_y ----
    #pragma unroll
    for (int i = 0; i < 4; ++i) {
        float o[4];
        unpack2(oacc[i][0], o[0], o[1]);
        unpack2(oacc[i][1], o[2], o[3]);
        const float rs = rinv[ty*4 + i];
        const int row = b*TT + qs + ty*4 + i;
        #pragma unroll
        for (int j = 0; j < 4; ++j) {
            const int col = h*DD + tx*4 + j;
            y[(size_t)row * CC + col] = o[j] * rs * gate[col];
        }
    }
}

// ============================================================
extern "C" void kernel_launch(void* const* d_in, const int* in_sizes, int n_in,
                              void* d_out, int out_size)
{
    const float* x      = (const float*)d_in[0];
    const float* mem    = (const float*)d_in[1];
    const float* W_qkv  = (const float*)d_in[2];
    const float* b_qkv  = (const float*)d_in[3];
    const float* W_proj = (const float*)d_in[4];
    const float* b_proj = (const float*)d_in[5];
    const float* gate   = (const float*)d_in[6];
    float* out = (float*)d_out;

    void* pq = nullptr; void* py = nullptr;
    cudaGetSymbolAddress(&pq, g_qkv);
    cudaGetSymbolAddress(&py, g_y);
    float* qkv = (float*)pq;
    float* ygat = (float*)py;

    const size_t attn_smem = ATTN_SMEM_FLOATS * sizeof(float);
    cudaFuncSetAttribute(attn_kernel, cudaFuncAttributeMaxDynamicSharedMemorySize,
                         (int)attn_smem);

    // 1) QKV = x @ W_qkv + b_qkv
    gemm_bias_kernel<<<dim3(C3/64, ROWS/64), 256>>>(x, W_qkv, b_qkv, qkv, C3, CC);

    // 2) attention (+gate) -> g_y
    attn_kernel<<<dim3(TT/64, HH, BB), 256, attn_smem>>>(qkv, mem, gate, ygat);

    // 3) out = g_y @ W_proj + b_proj
    gemm_bias_kernel<<<dim3(CC/64, ROWS/64), 256>>>(ygat, W_proj, b_proj, out, CC, CC);
}

// round 4
// speedup vs baseline: 1.7172x; 1.7172x over previous
#include <cuda_runtime.h>
#include <cuda_bf16.h>
#include <cstdint>

// Problem constants
#define BB   128
#define TT   256
#define CC   384
#define HH   6
#define DD   64
#define MM   128
#define WIN  64
#define C3   (3*CC)      // 1152
#define ROWS (BB*TT)     // 32768

// Scratch (allocation-free rule: __device__ globals)
__device__ float g_qkv[ROWS * C3];            // [B*T, 3C] fp32
__device__ float g_y[ROWS * CC];              // gated attention output fp32
__device__ __nv_bfloat16 g_xhi[ROWS * CC];
__device__ __nv_bfloat16 g_xlo[ROWS * CC];
__device__ __nv_bfloat16 g_yhi[ROWS * CC];
__device__ __nv_bfloat16 g_ylo[ROWS * CC];
__device__ __nv_bfloat16 g_wqt_hi[C3 * CC];   // W_qkv^T [1152,384]
__device__ __nv_bfloat16 g_wqt_lo[C3 * CC];
__device__ __nv_bfloat16 g_wpt_hi[CC * CC];   // W_proj^T [384,384]
__device__ __nv_bfloat16 g_wpt_lo[CC * CC];

typedef unsigned long long u64;

// ---------- packed f32x2 helpers (attention) ----------
__device__ __forceinline__ u64 pack2(float lo, float hi) {
    u64 r; asm("mov.b64 %0, {%1, %2};" : "=l"(r) : "f"(lo), "f"(hi)); return r;
}
__device__ __forceinline__ void unpack2(u64 v, float& lo, float& hi) {
    asm("mov.b64 {%0, %1}, %2;" : "=f"(lo), "=f"(hi) : "l"(v));
}
__device__ __forceinline__ void fma2(u64& d, u64 a, u64 b) {
    asm("fma.rn.f32x2 %0, %1, %2, %0;" : "+l"(d) : "l"(a), "l"(b));
}

// ---------- mma helpers (generic sm_80+ path; compiles on .target sm_103) ----------
__device__ __forceinline__ uint32_t smem_u32(const void* p) {
    uint32_t a;
    asm("{ .reg .u64 t; cvta.to.shared.u64 t, %1; cvt.u32.u64 %0, t; }" : "=r"(a) : "l"(p));
    return a;
}
__device__ __forceinline__ void ldsm_x4(uint32_t addr, uint32_t& r0, uint32_t& r1,
                                        uint32_t& r2, uint32_t& r3) {
    asm volatile("ldmatrix.sync.aligned.m8n8.x4.shared.b16 {%0,%1,%2,%3}, [%4];"
        : "=r"(r0), "=r"(r1), "=r"(r2), "=r"(r3) : "r"(addr));
}
__device__ __forceinline__ void mma16816(float* d, const uint32_t* a, const uint32_t* b) {
    asm volatile("mma.sync.aligned.m16n8k16.row.col.f32.bf16.bf16.f32 "
        "{%0,%1,%2,%3}, {%4,%5,%6,%7}, {%8,%9}, {%0,%1,%2,%3};"
        : "+f"(d[0]), "+f"(d[1]), "+f"(d[2]), "+f"(d[3])
        : "r"(a[0]), "r"(a[1]), "r"(a[2]), "r"(a[3]), "r"(b[0]), "r"(b[1]));
}
__device__ __forceinline__ void cp_async16(uint32_t dst, const void* src) {
    asm volatile("cp.async.cg.shared.global [%0], [%1], 16;" :: "r"(dst), "l"(src));
}
#define CP_COMMIT()  asm volatile("cp.async.commit_group;" ::: "memory")
#define CP_WAIT(n)   asm volatile("cp.async.wait_group %0;" :: "n"(n) : "memory")

// ============================================================
// split: f32 -> (hi bf16, lo bf16), lo = rn(x - hi)
// ============================================================
__global__ __launch_bounds__(256) void split_kernel(
    const float* __restrict__ in, __nv_bfloat16* __restrict__ hi,
    __nv_bfloat16* __restrict__ lo, int n4)
{
    int i = blockIdx.x * blockDim.x + threadIdx.x;
    if (i >= n4) return;
    float4 v = ((const float4*)in)[i];
    float vv[4] = {v.x, v.y, v.z, v.w};
    __nv_bfloat16 h[4], l[4];
    #pragma unroll
    for (int j = 0; j < 4; ++j) {
        h[j] = __float2bfloat16_rn(vv[j]);
        l[j] = __float2bfloat16_rn(vv[j] - __bfloat162float(h[j]));
    }
    ((__nv_bfloat162*)hi)[i*2+0] = __nv_bfloat162(h[0], h[1]);
    ((__nv_bfloat162*)hi)[i*2+1] = __nv_bfloat162(h[2], h[3]);
    ((__nv_bfloat162*)lo)[i*2+0] = __nv_bfloat162(l[0], l[1]);
    ((__nv_bfloat162*)lo)[i*2+1] = __nv_bfloat162(l[2], l[3]);
}

// ============================================================
// transpose + split: W[K][N] f32 -> Wt[N][K] bf16 hi/lo
// ============================================================
__global__ __launch_bounds__(256) void transpose_split_kernel(
    const float* __restrict__ W, __nv_bfloat16* __restrict__ hi,
    __nv_bfloat16* __restrict__ lo, int K, int N)
{
    __shared__ float t[32][33];
    const int k0 = blockIdx.y * 32, n0 = blockIdx.x * 32;
    const int tx = threadIdx.x, ty = threadIdx.y;   // 32 x 8
    #pragma unroll
    for (int i = ty; i < 32; i += 8)
        t[i][tx] = W[(size_t)(k0 + i) * N + n0 + tx];
    __syncthreads();
    #pragma unroll
    for (int i = ty; i < 32; i += 8) {
        float v = t[tx][i];     // = W[k0+tx][n0+i]
        __nv_bfloat16 h = __float2bfloat16_rn(v);
        size_t o = (size_t)(n0 + i) * K + k0 + tx;
        hi[o] = h;
        lo[o] = __float2bfloat16_rn(v - __bfloat162float(h));
    }
}

// ============================================================
// HMMA GEMM: C[M,N] = Ahi@Bhi^T + Alo@Bhi^T + Ahi@Blo^T + bias
// A*: [Mrows x K] bf16 row-major; B*: [N x K] bf16 row-major.
// CTA tile 128x128, BK=64 bf16 (128B swizzled rows),
// 8 warps: warp (wm=w&3, wn=w>>2) owns 32x64.
// cp.async double-buffer.
// ============================================================
#define BK 64
#define ATILE 16384
#define GEMM_SMEM (4 * 16384)     // 2 stages x (A 16KB + B 16KB)

__global__ __launch_bounds__(256) void mma_gemm_kernel(
    const __nv_bfloat16* __restrict__ Ahi, const __nv_bfloat16* __restrict__ Alo,
    const __nv_bfloat16* __restrict__ Bhi, const __nv_bfloat16* __restrict__ Blo,
    const float* __restrict__ bias, float* __restrict__ C, int N, int K)
{
    extern __shared__ __align__(1024) char smem[];
    const uint32_t sb = smem_u32(smem);
    const int tid = threadIdx.x;
    const int wid = tid >> 5, lane = tid & 31;
    const int wm = wid & 3, wn = wid >> 2;
    const int m0 = blockIdx.y * 128, n0 = blockIdx.x * 128;
    const int KCH = K / BK;          // 6
    const int NCH = 3 * KCH;         // 18

    // cp.async per-thread slots: 4 units of 16B per tile (A and B)
    // unit u = tid + i*256 ; r = u>>3, g = u&7
    uint32_t st_off[4];
    int ld_r[4];
    #pragma unroll
    for (int i = 0; i < 4; ++i) {
        const int u = tid + i * 256;
        const int r = u >> 3, g = u & 7;
        ld_r[i] = r;
        st_off[i] = (uint32_t)(r * 128 + ((g * 16) ^ ((r & 7) << 4)));
    }

    // ldmatrix lane addressing (byte offsets within a tile)
    // A: row = wm*32 + mt*16 + (lane&15), kbyte base = (lane>>4)*16
    const int arow0 = wm * 32 + (lane & 15);
    const uint32_t a_kx = (uint32_t)((lane >> 4) * 16);
    // B: row = wn*64 + np*16 + ((lane>>4)&1)*8 + (lane&7), kbyte base = ((lane>>3)&1)*16
    const int brow0 = wn * 64 + ((lane >> 4) & 1) * 8 + (lane & 7);
    const uint32_t b_kx = (uint32_t)(((lane >> 3) & 1) * 16);

    float acc[2][8][4];
    #pragma unroll
    for (int a = 0; a < 2; ++a)
        #pragma unroll
        for (int b = 0; b < 8; ++b)
            #pragma unroll
            for (int c = 0; c < 4; ++c) acc[a][b][c] = 0.f;

    // ---- prefetch chunk 0 ----
    {
        const __nv_bfloat16* Asrc = Ahi;
        const __nv_bfloat16* Bsrc = Bhi;
        #pragma unroll
        for (int i = 0; i < 4; ++i) {
            const int r = ld_r[i], g = (tid + i*256) & 7;
            cp_async16(sb + st_off[i],            Asrc + (size_t)(m0 + r) * K + g * 8);
            cp_async16(sb + ATILE + st_off[i],    Bsrc + (size_t)(n0 + r) * K + g * 8);
        }
        CP_COMMIT();
    }

    for (int c = 0; c < NCH; ++c) {
        const uint32_t buf = (uint32_t)(c & 1) * (2 * ATILE);
        if (c + 1 < NCH) {
            const int cn = c + 1;
            const int kc = (cn % KCH) * BK;
            const __nv_bfloat16* Asrc = (cn < KCH) ? Ahi : (cn < 2*KCH ? Alo : Ahi);
            const __nv_bfloat16* Bsrc = (cn < 2*KCH) ? Bhi : Blo;
            const uint32_t nbuf = (uint32_t)(cn & 1) * (2 * ATILE);
            #pragma unroll
            for (int i = 0; i < 4; ++i) {
                const int r = ld_r[i], g = (tid + i*256) & 7;
                cp_async16(sb + nbuf + st_off[i],         Asrc + (size_t)(m0 + r) * K + kc + g * 8);
                cp_async16(sb + nbuf + ATILE + st_off[i], Bsrc + (size_t)(n0 + r) * K + kc + g * 8);
            }
            CP_COMMIT();
            CP_WAIT(1);
        } else {
            CP_WAIT(0);
        }
        __syncthreads();

        const uint32_t abase = sb + buf;
        const uint32_t bbase = sb + buf + ATILE;
        #pragma unroll
        for (int ks = 0; ks < 4; ++ks) {
            const uint32_t ksb = (uint32_t)(ks * 32);
            uint32_t af[2][4];
            #pragma unroll
            for (int mt = 0; mt < 2; ++mt) {
                const int r = arow0 + mt * 16;
                const uint32_t addr = abase + (uint32_t)(r * 128) + ((ksb + a_kx) ^ ((uint32_t)(r & 7) << 4));
                ldsm_x4(addr, af[mt][0], af[mt][1], af[mt][2], af[mt][3]);
            }
            #pragma unroll
            for (int np = 0; np < 4; ++np) {
                uint32_t bf[4];
                const int r = brow0 + np * 16;
                const uint32_t addr = bbase + (uint32_t)(r * 128) + ((ksb + b_kx) ^ ((uint32_t)(r & 7) << 4));
                ldsm_x4(addr, bf[0], bf[1], bf[2], bf[3]);
                #pragma unroll
                for (int mt = 0; mt < 2; ++mt) {
                    mma16816(acc[mt][np*2+0], af[mt], &bf[0]);
                    mma16816(acc[mt][np*2+1], af[mt], &bf[2]);
                }
            }
        }
        __syncthreads();
    }

    // ---- epilogue ----
    #pragma unroll
    for (int mt = 0; mt < 2; ++mt) {
        const int mrow = m0 + wm * 32 + mt * 16 + (lane >> 2);
        #pragma unroll
        for (int nt = 0; nt < 8; ++nt) {
            const int col = n0 + wn * 64 + nt * 8 + (lane & 3) * 2;
            const float b0 = bias[col], b1 = bias[col + 1];
            float2 v0 = make_float2(acc[mt][nt][0] + b0, acc[mt][nt][1] + b1);
            float2 v1 = make_float2(acc[mt][nt][2] + b0, acc[mt][nt][3] + b1);
            *(float2*)&C[(size_t)mrow * N + col] = v0;
            *(float2*)&C[(size_t)(mrow + 8) * N + col] = v1;
        }
    }
}

// ============================================================
// Attention kernel (unchanged; scalar f32x2).
// ============================================================
#define QPAD 68
#define SROW 260
#define ATTN_SMEM_FLOATS (64*QPAD + 64*QPAD + 64*SROW + 64)

__global__ __launch_bounds__(256) void attn_kernel(
    const float* __restrict__ qkv, const float* __restrict__ mem,
    const float* __restrict__ gate, float* __restrict__ y)
{
    extern __shared__ float sm[];
    float* Qs   = sm;
    float* KVs  = sm + 64*QPAD;
    float* Ss   = sm + 2*64*QPAD;
    float* rinv = Ss + 64*SROW;

    const int qt = blockIdx.x, h = blockIdx.y, b = blockIdx.z;
    const int qs = qt * 64;
    const int tid = threadIdx.x;
    const int tx = tid & 15, ty = tid >> 4;

    {
        const int d = tid & 63;
        const int r0 = tid >> 6;
        #pragma unroll
        for (int r = r0; r < 64; r += 4)
            Qs[r*QPAD + d] = qkv[(size_t)(b*TT + qs + r) * C3 + h*DD + d];
    }

    for (int c = 0; c < 4; ++c) {
        __syncthreads();
        {
            const int d = tid & 63;
            const int r0 = tid >> 6;
            #pragma unroll
            for (int r = r0; r < 64; r += 4) {
                float val;
                if (c < 2) {
                    val = mem[(size_t)(c*64 + r) * CC + h*DD + d];
                } else {
                    const int p = qs - 64 + (c - 2)*64 + r;
                    val = (p >= 0) ? qkv[(size_t)(b*TT + p) * C3 + CC + h*DD + d] : 0.f;
                }
                KVs[r*QPAD + d] = val;
            }
        }
        __syncthreads();

        u64 acc[4][2] = {};
        for (int d4 = 0; d4 < DD; d4 += 4) {
            float kv[4][4], qv[4][4];
            #pragma unroll
            for (int j = 0; j < 4; ++j)
                *(float4*)&kv[j][0] = *(const float4*)&KVs[(tx*4 + j)*QPAD + d4];
            #pragma unroll
            for (int i = 0; i < 4; ++i)
                *(float4*)&qv[i][0] = *(const float4*)&Qs[(ty*4 + i)*QPAD + d4];
            #pragma unroll
            for (int dd = 0; dd < 4; ++dd) {
                u64 kp0 = pack2(kv[0][dd], kv[1][dd]);
                u64 kp1 = pack2(kv[2][dd], kv[3][dd]);
                #pragma unroll
                for (int i = 0; i < 4; ++i) {
                    u64 qd = pack2(qv[i][dd], qv[i][dd]);
                    fma2(acc[i][0], qd, kp0);
                    fma2(acc[i][1], qd, kp1);
                }
            }
        }
        #pragma unroll
        for (int i = 0; i < 4; ++i) {
            float s[4];
            unpack2(acc[i][0], s[0], s[1]);
            unpack2(acc[i][1], s[2], s[3]);
            const int qi = qs + ty*4 + i;
            #pragma unroll
            for (int j = 0; j < 4; ++j) {
                const int ks = c*64 + tx*4 + j;
                bool valid;
                if (ks < MM) {
                    valid = true;
                } else {
                    const int jj = qs - 64 + (ks - MM);
                    valid = (jj >= 0) && (jj <= qi) && (qi - jj <= WIN);
                }
                Ss[(ty*4 + i)*SROW + ks] = valid ? s[j] * 0.125f : -1e30f;
            }
        }
    }
    __syncthreads();

    {
        const int w = tid >> 5, l = tid & 31;
        for (int rr = 0; rr < 8; ++rr) {
            const int r = w*8 + rr;
            float* row = &Ss[r*SROW];
            float mx = -1e30f;
            #pragma unroll
            for (int cidx = l; cidx < 256; cidx += 32)
                mx = fmaxf(mx, row[cidx]);
            #pragma unroll
            for (int off = 16; off > 0; off >>= 1)
                mx = fmaxf(mx, __shfl_xor_sync(0xFFFFFFFFu, mx, off));
            float sum = 0.f;
            #pragma unroll
            for (int cidx = l; cidx < 256; cidx += 32) {
                float e = __expf(row[cidx] - mx);
                row[cidx] = e;
                sum += e;
            }
            #pragma unroll
            for (int off = 16; off > 0; off >>= 1)
                sum += __shfl_xor_sync(0xFFFFFFFFu, sum, off);
            if (l == 0) rinv[r] = 1.0f / sum;
        }
    }

    u64 oacc[4][2] = {};
    for (int c = 0; c < 4; ++c) {
        __syncthreads();
        {
            const int d = tid & 63;
            const int r0 = tid >> 6;
            #pragma unroll
            for (int r = r0; r < 64; r += 4) {
                float val;
                if (c < 2) {
                    val = mem[(size_t)(c*64 + r) * CC + h*DD + d];
                } else {
                    const int p = qs - 64 + (c - 2)*64 + r;
                    val = (p >= 0) ? qkv[(size_t)(b*TT + p) * C3 + 2*CC + h*DD + d] : 0.f;
                }
                KVs[r*QPAD + d] = val;
            }
        }
        __syncthreads();

        for (int kk4 = 0; kk4 < 64; kk4 += 4) {
            float pv[4][4], vv[4][4];
            #pragma unroll
            for (int i = 0; i < 4; ++i)
                *(float4*)&pv[i][0] = *(const float4*)&Ss[(ty*4 + i)*SROW + c*64 + kk4];
            #pragma unroll
            for (int r = 0; r < 4; ++r)
                *(float4*)&vv[r][0] = *(const float4*)&KVs[(kk4 + r)*QPAD + tx*4];
            #pragma unroll
            for (int r = 0; r < 4; ++r) {
                u64 vp0 = pack2(vv[r][0], vv[r][1]);
                u64 vp1 = pack2(vv[r][2], vv[r][3]);
                #pragma unroll
                for (int i = 0; i < 4; ++i) {
                    u64 pd = pack2(pv[i][r], pv[i][r]);
                    fma2(oacc[i][0], pd, vp0);
                    fma2(oacc[i][1], pd, vp1);
                }
            }
        }
    }

    #pragma unroll
    for (int i = 0; i < 4; ++i) {
        float o[4];
        unpack2(oacc[i][0], o[0], o[1]);
        unpack2(oacc[i][1], o[2], o[3]);
        const float rs = rinv[ty*4 + i];
        const int row = b*TT + qs + ty*4 + i;
        #pragma unroll
        for (int j = 0; j < 4; ++j) {
            const int col = h*DD + tx*4 + j;
            y[(size_t)row * CC + col] = o[j] * rs * gate[col];
        }
    }
}

// ============================================================
extern "C" void kernel_launch(void* const* d_in, const int* in_sizes, int n_in,
                              void* d_out, int out_size)
{
    const float* x      = (const float*)d_in[0];
    const float* mem    = (const float*)d_in[1];
    const float* W_qkv  = (const float*)d_in[2];
    const float* b_qkv  = (const float*)d_in[3];
    const float* W_proj = (const float*)d_in[4];
    const float* b_proj = (const float*)d_in[5];
    const float* gate   = (const float*)d_in[6];
    float* out = (float*)d_out;

    void *pq, *py, *pxh, *pxl, *pyh, *pyl, *pwqh, *pwql, *pwph, *pwpl;
    cudaGetSymbolAddress(&pq, g_qkv);
    cudaGetSymbolAddress(&py, g_y);
    cudaGetSymbolAddress(&pxh, g_xhi);  cudaGetSymbolAddress(&pxl, g_xlo);
    cudaGetSymbolAddress(&pyh, g_yhi);  cudaGetSymbolAddress(&pyl, g_ylo);
    cudaGetSymbolAddress(&pwqh, g_wqt_hi); cudaGetSymbolAddress(&pwql, g_wqt_lo);
    cudaGetSymbolAddress(&pwph, g_wpt_hi); cudaGetSymbolAddress(&pwpl, g_wpt_lo);

    float* qkv = (float*)pq;
    float* ygat = (float*)py;

    cudaFuncSetAttribute(mma_gemm_kernel,
        cudaFuncAttributeMaxDynamicSharedMemorySize, GEMM_SMEM);
    cudaFuncSetAttribute(attn_kernel,
        cudaFuncAttributeMaxDynamicSharedMemorySize,
        (int)(ATTN_SMEM_FLOATS * sizeof(float)));

    const int n4 = ROWS * CC / 4;

    // 1) split x into bf16 hi/lo
    split_kernel<<<(n4 + 255) / 256, 256>>>(x, (__nv_bfloat16*)pxh, (__nv_bfloat16*)pxl, n4);

    // 2) transpose+split weights
    transpose_split_kernel<<<dim3(C3/32, CC/32), dim3(32, 8)>>>(
        W_qkv, (__nv_bfloat16*)pwqh, (__nv_bfloat16*)pwql, CC, C3);
    transpose_split_kernel<<<dim3(CC/32, CC/32), dim3(32, 8)>>>(
        W_proj, (__nv_bfloat16*)pwph, (__nv_bfloat16*)pwpl, CC, CC);

    // 3) QKV = x @ W_qkv + b_qkv  (HMMA, 3-term split)
    mma_gemm_kernel<<<dim3(C3/128, ROWS/128), 256, GEMM_SMEM>>>(
        (const __nv_bfloat16*)pxh, (const __nv_bfloat16*)pxl,
        (const __nv_bfloat16*)pwqh, (const __nv_bfloat16*)pwql,
        b_qkv, qkv, C3, CC);

    // 4) attention (+gate) -> g_y
    attn_kernel<<<dim3(TT/64, HH, BB), 256, ATTN_SMEM_FLOATS * sizeof(float)>>>(
        qkv, mem, gate, ygat);

    // 5) split y
    split_kernel<<<(n4 + 255) / 256, 256>>>(ygat, (__nv_bfloat16*)pyh, (__nv_bfloat16*)pyl, n4);

    // 6) out = y @ W_proj + b_proj (HMMA, 3-term split)
    mma_gemm_kernel<<<dim3(CC/128, ROWS/128), 256, GEMM_SMEM>>>(
        (const __nv_bfloat16*)pyh, (const __nv_bfloat16*)pyl,
        (const __nv_bfloat16*)pwph, (const __nv_bfloat16*)pwpl,
        b_proj, out, CC, CC);
}

// round 5
// speedup vs baseline: 5.8200x; 3.3893x over previous
#include <cuda_runtime.h>
#include <cuda_bf16.h>
#include <cuda_fp16.h>
#include <cstdint>

// Problem constants
#define BB   128
#define TT   256
#define CC   384
#define HH   6
#define DD   64
#define MM   128
#define WIN  64
#define C3   (3*CC)      // 1152
#define ROWS (BB*TT)     // 32768

// Scratch (allocation-free rule: __device__ globals)
__device__ __half g_qkv_h[ROWS * C3];         // fp16 qkv
__device__ float  g_y[ROWS * CC];             // gated attention output fp32
__device__ __half g_xh[ROWS * CC];            // x fp16
__device__ __half g_wqt_h[C3 * CC];           // W_qkv^T fp16 [1152,384]
__device__ __half g_mem_h[MM * CC];           // memory fp16
__device__ __nv_bfloat16 g_yhi[ROWS * CC];
__device__ __nv_bfloat16 g_ylo[ROWS * CC];
__device__ __nv_bfloat16 g_wpt_hi[CC * CC];   // W_proj^T bf16 hi/lo
__device__ __nv_bfloat16 g_wpt_lo[CC * CC];

typedef unsigned long long u64;

// ---------- mma helpers (generic sm_80+ path) ----------
__device__ __forceinline__ uint32_t smem_u32(const void* p) {
    uint32_t a;
    asm("{ .reg .u64 t; cvta.to.shared.u64 t, %1; cvt.u32.u64 %0, t; }" : "=r"(a) : "l"(p));
    return a;
}
__device__ __forceinline__ void ldsm_x4(uint32_t addr, uint32_t& r0, uint32_t& r1,
                                        uint32_t& r2, uint32_t& r3) {
    asm volatile("ldmatrix.sync.aligned.m8n8.x4.shared.b16 {%0,%1,%2,%3}, [%4];"
        : "=r"(r0), "=r"(r1), "=r"(r2), "=r"(r3) : "r"(addr));
}
__device__ __forceinline__ void ldsm_x4t(uint32_t addr, uint32_t& r0, uint32_t& r1,
                                         uint32_t& r2, uint32_t& r3) {
    asm volatile("ldmatrix.sync.aligned.m8n8.x4.trans.shared.b16 {%0,%1,%2,%3}, [%4];"
        : "=r"(r0), "=r"(r1), "=r"(r2), "=r"(r3) : "r"(addr));
}
__device__ __forceinline__ void mma_bf16(float* d, const uint32_t* a, const uint32_t* b) {
    asm volatile("mma.sync.aligned.m16n8k16.row.col.f32.bf16.bf16.f32 "
        "{%0,%1,%2,%3}, {%4,%5,%6,%7}, {%8,%9}, {%0,%1,%2,%3};"
        : "+f"(d[0]), "+f"(d[1]), "+f"(d[2]), "+f"(d[3])
        : "r"(a[0]), "r"(a[1]), "r"(a[2]), "r"(a[3]), "r"(b[0]), "r"(b[1]));
}
__device__ __forceinline__ void mma_f16(float* d, const uint32_t* a, const uint32_t* b) {
    asm volatile("mma.sync.aligned.m16n8k16.row.col.f32.f16.f16.f32 "
        "{%0,%1,%2,%3}, {%4,%5,%6,%7}, {%8,%9}, {%0,%1,%2,%3};"
        : "+f"(d[0]), "+f"(d[1]), "+f"(d[2]), "+f"(d[3])
        : "r"(a[0]), "r"(a[1]), "r"(a[2]), "r"(a[3]), "r"(b[0]), "r"(b[1]));
}
__device__ __forceinline__ void cp_async16(uint32_t dst, const void* src) {
    asm volatile("cp.async.cg.shared.global [%0], [%1], 16;" :: "r"(dst), "l"(src));
}
#define CP_COMMIT()  asm volatile("cp.async.commit_group;" ::: "memory")
#define CP_WAIT(n)   asm volatile("cp.async.wait_group %0;" :: "n"(n) : "memory")
#define SWZ(r, gb)   ((uint32_t)((r) * 128 + (((gb)) ^ (((r) & 7) << 4))))

// ============================================================
// converts
// ============================================================
__global__ __launch_bounds__(256) void cvt_f16_kernel(
    const float* __restrict__ in, __half* __restrict__ out, int n4)
{
    int i = blockIdx.x * blockDim.x + threadIdx.x;
    if (i >= n4) return;
    float4 v = ((const float4*)in)[i];
    ((__half2*)out)[i*2+0] = __floats2half2_rn(v.x, v.y);
    ((__half2*)out)[i*2+1] = __floats2half2_rn(v.z, v.w);
}

__global__ __launch_bounds__(256) void split_kernel(
    const float* __restrict__ in, __nv_bfloat16* __restrict__ hi,
    __nv_bfloat16* __restrict__ lo, int n4)
{
    int i = blockIdx.x * blockDim.x + threadIdx.x;
    if (i >= n4) return;
    float4 v = ((const float4*)in)[i];
    float vv[4] = {v.x, v.y, v.z, v.w};
    __nv_bfloat16 h[4], l[4];
    #pragma unroll
    for (int j = 0; j < 4; ++j) {
        h[j] = __float2bfloat16_rn(vv[j]);
        l[j] = __float2bfloat16_rn(vv[j] - __bfloat162float(h[j]));
    }
    ((__nv_bfloat162*)hi)[i*2+0] = __nv_bfloat162(h[0], h[1]);
    ((__nv_bfloat162*)hi)[i*2+1] = __nv_bfloat162(h[2], h[3]);
    ((__nv_bfloat162*)lo)[i*2+0] = __nv_bfloat162(l[0], l[1]);
    ((__nv_bfloat162*)lo)[i*2+1] = __nv_bfloat162(l[2], l[3]);
}

__global__ __launch_bounds__(256) void transpose_cvt_kernel(
    const float* __restrict__ W, __half* __restrict__ out, int K, int N)
{
    __shared__ float t[32][33];
    const int k0 = blockIdx.y * 32, n0 = blockIdx.x * 32;
    const int tx = threadIdx.x, ty = threadIdx.y;
    #pragma unroll
    for (int i = ty; i < 32; i += 8)
        t[i][tx] = W[(size_t)(k0 + i) * N + n0 + tx];
    __syncthreads();
    #pragma unroll
    for (int i = ty; i < 32; i += 8)
        out[(size_t)(n0 + i) * K + k0 + tx] = __float2half(t[tx][i]);
}

__global__ __launch_bounds__(256) void transpose_split_kernel(
    const float* __restrict__ W, __nv_bfloat16* __restrict__ hi,
    __nv_bfloat16* __restrict__ lo, int K, int N)
{
    __shared__ float t[32][33];
    const int k0 = blockIdx.y * 32, n0 = blockIdx.x * 32;
    const int tx = threadIdx.x, ty = threadIdx.y;
    #pragma unroll
    for (int i = ty; i < 32; i += 8)
        t[i][tx] = W[(size_t)(k0 + i) * N + n0 + tx];
    __syncthreads();
    #pragma unroll
    for (int i = ty; i < 32; i += 8) {
        float v = t[tx][i];
        __nv_bfloat16 h = __float2bfloat16_rn(v);
        size_t o = (size_t)(n0 + i) * K + k0 + tx;
        hi[o] = h;
        lo[o] = __float2bfloat16_rn(v - __bfloat162float(h));
    }
}

// ============================================================
// fp16 single-pass GEMM: C_h[M,N] = A@B^T + bias (fp16 in/out, fp32 acc)
// ============================================================
#define BK 64
#define ATILE 16384
#define GEMM_SMEM (4 * 16384)

__global__ __launch_bounds__(256) void mma_gemm_f16_kernel(
    const __half* __restrict__ A, const __half* __restrict__ B,
    const float* __restrict__ bias, __half* __restrict__ C, int N, int K)
{
    extern __shared__ __align__(1024) char smem[];
    const uint32_t sb = smem_u32(smem);
    const int tid = threadIdx.x;
    const int wid = tid >> 5, lane = tid & 31;
    const int wm = wid & 3, wn = wid >> 2;
    const int m0 = blockIdx.y * 128, n0 = blockIdx.x * 128;
    const int NCH = K / BK;   // 6

    uint32_t st_off[4];
    int ld_r[4];
    #pragma unroll
    for (int i = 0; i < 4; ++i) {
        const int u = tid + i * 256;
        const int r = u >> 3, g = u & 7;
        ld_r[i] = r;
        st_off[i] = SWZ(r, g * 16);
    }

    const int arow0 = wm * 32 + (lane & 15);
    const uint32_t a_kx = (uint32_t)((lane >> 4) * 16);
    const int brow0 = wn * 64 + ((lane >> 4) & 1) * 8 + (lane & 7);
    const uint32_t b_kx = (uint32_t)(((lane >> 3) & 1) * 16);

    float acc[2][8][4];
    #pragma unroll
    for (int a = 0; a < 2; ++a)
        #pragma unroll
        for (int b = 0; b < 8; ++b)
            #pragma unroll
            for (int c = 0; c < 4; ++c) acc[a][b][c] = 0.f;

    #pragma unroll
    for (int i = 0; i < 4; ++i) {
        const int r = ld_r[i], g = (tid + i*256) & 7;
        cp_async16(sb + st_off[i],         A + (size_t)(m0 + r) * K + g * 8);
        cp_async16(sb + ATILE + st_off[i], B + (size_t)(n0 + r) * K + g * 8);
    }
    CP_COMMIT();

    for (int c = 0; c < NCH; ++c) {
        const uint32_t buf = (uint32_t)(c & 1) * (2 * ATILE);
        if (c + 1 < NCH) {
            const int kc = (c + 1) * BK;
            const uint32_t nbuf = (uint32_t)((c + 1) & 1) * (2 * ATILE);
            #pragma unroll
            for (int i = 0; i < 4; ++i) {
                const int r = ld_r[i], g = (tid + i*256) & 7;
                cp_async16(sb + nbuf + st_off[i],         A + (size_t)(m0 + r) * K + kc + g * 8);
                cp_async16(sb + nbuf + ATILE + st_off[i], B + (size_t)(n0 + r) * K + kc + g * 8);
            }
            CP_COMMIT();
            CP_WAIT(1);
        } else {
            CP_WAIT(0);
        }
        __syncthreads();

        const uint32_t abase = sb + buf;
        const uint32_t bbase = sb + buf + ATILE;
        #pragma unroll
        for (int ks = 0; ks < 4; ++ks) {
            const uint32_t ksb = (uint32_t)(ks * 32);
            uint32_t af[2][4];
            #pragma unroll
            for (int mt = 0; mt < 2; ++mt) {
                const int r = arow0 + mt * 16;
                ldsm_x4(abase + SWZ(r, ksb + a_kx), af[mt][0], af[mt][1], af[mt][2], af[mt][3]);
            }
            #pragma unroll
            for (int np = 0; np < 4; ++np) {
                uint32_t bf[4];
                const int r = brow0 + np * 16;
                ldsm_x4(bbase + SWZ(r, ksb + b_kx), bf[0], bf[1], bf[2], bf[3]);
                #pragma unroll
                for (int mt = 0; mt < 2; ++mt) {
                    mma_f16(acc[mt][np*2+0], af[mt], &bf[0]);
                    mma_f16(acc[mt][np*2+1], af[mt], &bf[2]);
                }
            }
        }
        __syncthreads();
    }

    #pragma unroll
    for (int mt = 0; mt < 2; ++mt) {
        const int mrow = m0 + wm * 32 + mt * 16 + (lane >> 2);
        #pragma unroll
        for (int nt = 0; nt < 8; ++nt) {
            const int col = n0 + wn * 64 + nt * 8 + (lane & 3) * 2;
            const float b0 = bias[col], b1 = bias[col + 1];
            *(__half2*)&C[(size_t)mrow * N + col] =
                __floats2half2_rn(acc[mt][nt][0] + b0, acc[mt][nt][1] + b1);
            *(__half2*)&C[(size_t)(mrow + 8) * N + col] =
                __floats2half2_rn(acc[mt][nt][2] + b0, acc[mt][nt][3] + b1);
        }
    }
}

// ============================================================
// bf16 3-term split GEMM (for proj): C = Ahi@Bhi^T + Alo@Bhi^T + Ahi@Blo^T + bias
// ============================================================
__global__ __launch_bounds__(256) void mma_gemm_kernel(
    const __nv_bfloat16* __restrict__ Ahi, const __nv_bfloat16* __restrict__ Alo,
    const __nv_bfloat16* __restrict__ Bhi, const __nv_bfloat16* __restrict__ Blo,
    const float* __restrict__ bias, float* __restrict__ C, int N, int K)
{
    extern __shared__ __align__(1024) char smem[];
    const uint32_t sb = smem_u32(smem);
    const int tid = threadIdx.x;
    const int wid = tid >> 5, lane = tid & 31;
    const int wm = wid & 3, wn = wid >> 2;
    const int m0 = blockIdx.y * 128, n0 = blockIdx.x * 128;
    const int KCH = K / BK;
    const int NCH = 3 * KCH;

    uint32_t st_off[4];
    int ld_r[4];
    #pragma unroll
    for (int i = 0; i < 4; ++i) {
        const int u = tid + i * 256;
        const int r = u >> 3, g = u & 7;
        ld_r[i] = r;
        st_off[i] = SWZ(r, g * 16);
    }

    const int arow0 = wm * 32 + (lane & 15);
    const uint32_t a_kx = (uint32_t)((lane >> 4) * 16);
    const int brow0 = wn * 64 + ((lane >> 4) & 1) * 8 + (lane & 7);
    const uint32_t b_kx = (uint32_t)(((lane >> 3) & 1) * 16);

    float acc[2][8][4];
    #pragma unroll
    for (int a = 0; a < 2; ++a)
        #pragma unroll
        for (int b = 0; b < 8; ++b)
            #pragma unroll
            for (int c = 0; c < 4; ++c) acc[a][b][c] = 0.f;

    {
        #pragma unroll
        for (int i = 0; i < 4; ++i) {
            const int r = ld_r[i], g = (tid + i*256) & 7;
            cp_async16(sb + st_off[i],         Ahi + (size_t)(m0 + r) * K + g * 8);
            cp_async16(sb + ATILE + st_off[i], Bhi + (size_t)(n0 + r) * K + g * 8);
        }
        CP_COMMIT();
    }

    for (int c = 0; c < NCH; ++c) {
        const uint32_t buf = (uint32_t)(c & 1) * (2 * ATILE);
        if (c + 1 < NCH) {
            const int cn = c + 1;
            const int kc = (cn % KCH) * BK;
            const __nv_bfloat16* Asrc = (cn < KCH) ? Ahi : (cn < 2*KCH ? Alo : Ahi);
            const __nv_bfloat16* Bsrc = (cn < 2*KCH) ? Bhi : Blo;
            const uint32_t nbuf = (uint32_t)(cn & 1) * (2 * ATILE);
            #pragma unroll
            for (int i = 0; i < 4; ++i) {
                const int r = ld_r[i], g = (tid + i*256) & 7;
                cp_async16(sb + nbuf + st_off[i],         Asrc + (size_t)(m0 + r) * K + kc + g * 8);
                cp_async16(sb + nbuf + ATILE + st_off[i], Bsrc + (size_t)(n0 + r) * K + kc + g * 8);
            }
            CP_COMMIT();
            CP_WAIT(1);
        } else {
            CP_WAIT(0);
        }
        __syncthreads();

        const uint32_t abase = sb + buf;
        const uint32_t bbase = sb + buf + ATILE;
        #pragma unroll
        for (int ks = 0; ks < 4; ++ks) {
            const uint32_t ksb = (uint32_t)(ks * 32);
            uint32_t af[2][4];
            #pragma unroll
            for (int mt = 0; mt < 2; ++mt) {
                const int r = arow0 + mt * 16;
                ldsm_x4(abase + SWZ(r, ksb + a_kx), af[mt][0], af[mt][1], af[mt][2], af[mt][3]);
            }
            #pragma unroll
            for (int np = 0; np < 4; ++np) {
                uint32_t bf[4];
                const int r = brow0 + np * 16;
                ldsm_x4(bbase + SWZ(r, ksb + b_kx), bf[0], bf[1], bf[2], bf[3]);
                #pragma unroll
                for (int mt = 0; mt < 2; ++mt) {
                    mma_bf16(acc[mt][np*2+0], af[mt], &bf[0]);
                    mma_bf16(acc[mt][np*2+1], af[mt], &bf[2]);
                }
            }
        }
        __syncthreads();
    }

    #pragma unroll
    for (int mt = 0; mt < 2; ++mt) {
        const int mrow = m0 + wm * 32 + mt * 16 + (lane >> 2);
        #pragma unroll
        for (int nt = 0; nt < 8; ++nt) {
            const int col = n0 + wn * 64 + nt * 8 + (lane & 3) * 2;
            const float b0 = bias[col], b1 = bias[col + 1];
            *(float2*)&C[(size_t)mrow * N + col] =
                make_float2(acc[mt][nt][0] + b0, acc[mt][nt][1] + b1);
            *(float2*)&C[(size_t)(mrow + 8) * N + col] =
                make_float2(acc[mt][nt][2] + b0, acc[mt][nt][3] + b1);
        }
    }
}

// ============================================================
// Flash-style HMMA attention.
// Block = (q-tile 64, head, batch), 128 threads = 4 warps.
// Warp w: q rows w*16..w*16+15. Keys: 0-127 mem, 128-255 self window qs-64..qs+63.
// fp16 Q/K/V in smem, fp32 online softmax in regs, P@V via frag reuse.
// ============================================================
#define QS_OFF 0
#define KS_OFF 8192
#define VS_OFF 40960
#define ATTN_SMEM 73728

__global__ __launch_bounds__(128) void attn_flash_kernel(
    const __half* __restrict__ qkv, const __half* __restrict__ memh,
    const float* __restrict__ gate, float* __restrict__ y)
{
    extern __shared__ __align__(1024) char smem[];
    const uint32_t sb = smem_u32(smem);
    const int qt = blockIdx.x, h = blockIdx.y, b = blockIdx.z;
    const int qs = qt * 64;
    const int tid = threadIdx.x;
    const int wid = tid >> 5, lane = tid & 31;

    // ---- stage Q, K, V via cp.async ----
    // Q: 64 rows x 8 units
    #pragma unroll
    for (int i = 0; i < 4; ++i) {
        const int u = tid + i * 128;
        const int r = u >> 3, g = u & 7;
        cp_async16(sb + QS_OFF + SWZ(r, g * 16),
                   qkv + (size_t)(b*TT + qs + r) * C3 + h*DD + g*8);
    }
    // K, V: 256 rows x 8 units each
    #pragma unroll
    for (int i = 0; i < 16; ++i) {
        const int u = tid + i * 128;
        const int r = u >> 3, g = u & 7;
        if (r < MM) {
            cp_async16(sb + KS_OFF + SWZ(r, g * 16), memh + (size_t)r * CC + h*DD + g*8);
            cp_async16(sb + VS_OFF + SWZ(r, g * 16), memh + (size_t)r * CC + h*DD + g*8);
        } else {
            const int p = qs - 64 + (r - MM);
            if (p >= 0) {
                cp_async16(sb + KS_OFF + SWZ(r, g * 16),
                           qkv + (size_t)(b*TT + p) * C3 + CC + h*DD + g*8);
                cp_async16(sb + VS_OFF + SWZ(r, g * 16),
                           qkv + (size_t)(b*TT + p) * C3 + 2*CC + h*DD + g*8);
            } else {
                const uint4 z = make_uint4(0,0,0,0);
                *(uint4*)(smem + KS_OFF + SWZ(r, g * 16)) = z;
                *(uint4*)(smem + VS_OFF + SWZ(r, g * 16)) = z;
            }
        }
    }
    CP_COMMIT();
    CP_WAIT(0);
    __syncthreads();

    const int qb = wid * 16;
    const int r_lo = lane >> 2;            // row within 16-tile (and +8)
    const int c_lo = (lane & 3) * 2;       // col pair base within n8 tile
    const int qi0 = qs + qb + r_lo;
    const int qi1 = qi0 + 8;

    const uint32_t a_kx = (uint32_t)((lane >> 4) * 16);
    const int arow = qb + (lane & 15);
    const int brow_base = ((lane >> 4) & 1) * 8 + (lane & 7);
    const uint32_t b_kx = (uint32_t)(((lane >> 3) & 1) * 16);
    const int vrow_base = ((lane >> 3) & 1) * 8 + (lane & 7);
    const uint32_t v_nx = (uint32_t)((lane >> 4) * 16);

    float O[8][4];
    #pragma unroll
    for (int t = 0; t < 8; ++t)
        #pragma unroll
        for (int e = 0; e < 4; ++e) O[t][e] = 0.f;
    float m0 = -1e30f, m1 = -1e30f, l0 = 0.f, l1 = 0.f;

    for (int c = 0; c < 4; ++c) {
        if (qt == 0 && c == 2) continue;   // self keys p in [-64,-1]: all masked
        const int kb = c * 64;

        // ---- S = Q K^T ----
        float s[8][4];
        #pragma unroll
        for (int t = 0; t < 8; ++t)
            #pragma unroll
            for (int e = 0; e < 4; ++e) s[t][e] = 0.f;
        #pragma unroll
        for (int ks = 0; ks < 4; ++ks) {
            const uint32_t ksb = (uint32_t)(ks * 32);
            uint32_t af[4];
            ldsm_x4(sb + QS_OFF + SWZ(arow, ksb + a_kx), af[0], af[1], af[2], af[3]);
            #pragma unroll
            for (int np = 0; np < 4; ++np) {
                uint32_t bf[4];
                const int r = kb + np * 16 + brow_base;
                ldsm_x4(sb + KS_OFF + SWZ(r, ksb + b_kx), bf[0], bf[1], bf[2], bf[3]);
                mma_f16(s[np*2+0], af, &bf[0]);
                mma_f16(s[np*2+1], af, &bf[2]);
            }
        }

        // ---- scale + mask ----
        #pragma unroll
        for (int t = 0; t < 8; ++t) {
            #pragma unroll
            for (int e = 0; e < 4; ++e) {
                const int key = kb + t*8 + c_lo + (e & 1);
                const int qi = (e < 2) ? qi0 : qi1;
                bool valid = true;
                if (key >= MM) {
                    const int p = qs - 64 + (key - MM);
                    valid = (p >= 0) && (p <= qi) && (qi - p <= WIN);
                }
                s[t][e] = valid ? s[t][e] * 0.125f : -1e30f;
            }
        }

        // ---- online softmax ----
        float cm0 = -1e30f, cm1 = -1e30f;
        #pragma unroll
        for (int t = 0; t < 8; ++t) {
            cm0 = fmaxf(cm0, fmaxf(s[t][0], s[t][1]));
            cm1 = fmaxf(cm1, fmaxf(s[t][2], s[t][3]));
        }
        cm0 = fmaxf(cm0, __shfl_xor_sync(0xFFFFFFFFu, cm0, 1));
        cm0 = fmaxf(cm0, __shfl_xor_sync(0xFFFFFFFFu, cm0, 2));
        cm1 = fmaxf(cm1, __shfl_xor_sync(0xFFFFFFFFu, cm1, 1));
        cm1 = fmaxf(cm1, __shfl_xor_sync(0xFFFFFFFFu, cm1, 2));
        const float mn0 = fmaxf(m0, cm0), mn1 = fmaxf(m1, cm1);
        const float sc0 = __expf(m0 - mn0), sc1 = __expf(m1 - mn1);
        m0 = mn0; m1 = mn1;
        l0 *= sc0; l1 *= sc1;
        #pragma unroll
        for (int t = 0; t < 8; ++t) {
            O[t][0] *= sc0; O[t][1] *= sc0;
            O[t][2] *= sc1; O[t][3] *= sc1;
        }
        uint32_t ph[8][2];
        #pragma unroll
        for (int t = 0; t < 8; ++t) {
            const float p0 = __expf(s[t][0] - mn0), p1 = __expf(s[t][1] - mn0);
            const float p2 = __expf(s[t][2] - mn1), p3 = __expf(s[t][3] - mn1);
            l0 += p0 + p1; l1 += p2 + p3;
            __half2 h01 = __floats2half2_rn(p0, p1);
            __half2 h23 = __floats2half2_rn(p2, p3);
            ph[t][0] = *(uint32_t*)&h01;
            ph[t][1] = *(uint32_t*)&h23;
        }

        // ---- O += P V ----
        #pragma unroll
        for (int ks = 0; ks < 4; ++ks) {
            uint32_t a[4] = { ph[2*ks][0], ph[2*ks][1], ph[2*ks+1][0], ph[2*ks+1][1] };
            #pragma unroll
            for (int g = 0; g < 4; ++g) {
                uint32_t vb[4];
                const int r = kb + ks * 16 + vrow_base;
                ldsm_x4t(sb + VS_OFF + SWZ(r, (uint32_t)(g * 32) + v_nx),
                         vb[0], vb[1], vb[2], vb[3]);
                mma_f16(O[g*2+0], a, &vb[0]);
                mma_f16(O[g*2+1], a, &vb[2]);
            }
        }
    }

    // ---- finalize ----
    l0 += __shfl_xor_sync(0xFFFFFFFFu, l0, 1);
    l0 += __shfl_xor_sync(0xFFFFFFFFu, l0, 2);
    l1 += __shfl_xor_sync(0xFFFFFFFFu, l1, 1);
    l1 += __shfl_xor_sync(0xFFFFFFFFu, l1, 2);
    const float rc0 = 1.0f / l0, rc1 = 1.0f / l1;

    const size_t row0 = (size_t)(b*TT + qs + qb + r_lo);
    #pragma unroll
    for (int t = 0; t < 8; ++t) {
        const int col = h*DD + t*8 + c_lo;
        const float g0 = gate[col], g1 = gate[col + 1];
        *(float2*)&y[row0 * CC + col] =
            make_float2(O[t][0] * rc0 * g0, O[t][1] * rc0 * g1);
        *(float2*)&y[(row0 + 8) * CC + col] =
            make_float2(O[t][2] * rc1 * g0, O[t][3] * rc1 * g1);
    }
}

// ============================================================
extern "C" void kernel_launch(void* const* d_in, const int* in_sizes, int n_in,
                              void* d_out, int out_size)
{
    const float* x      = (const float*)d_in[0];
    const float* mem    = (const float*)d_in[1];
    const float* W_qkv  = (const float*)d_in[2];
    const float* b_qkv  = (const float*)d_in[3];
    const float* W_proj = (const float*)d_in[4];
    const float* b_proj = (const float*)d_in[5];
    const float* gate   = (const float*)d_in[6];
    float* out = (float*)d_out;

    void *pqh, *py, *pxh, *pwqh, *pmh, *pyh, *pyl, *pwph, *pwpl;
    cudaGetSymbolAddress(&pqh, g_qkv_h);
    cudaGetSymbolAddress(&py, g_y);
    cudaGetSymbolAddress(&pxh, g_xh);
    cudaGetSymbolAddress(&pwqh, g_wqt_h);
    cudaGetSymbolAddress(&pmh, g_mem_h);
    cudaGetSymbolAddress(&pyh, g_yhi); cudaGetSymbolAddress(&pyl, g_ylo);
    cudaGetSymbolAddress(&pwph, g_wpt_hi); cudaGetSymbolAddress(&pwpl, g_wpt_lo);

    cudaFuncSetAttribute(mma_gemm_f16_kernel,
        cudaFuncAttributeMaxDynamicSharedMemorySize, GEMM_SMEM);
    cudaFuncSetAttribute(mma_gemm_kernel,
        cudaFuncAttributeMaxDynamicSharedMemorySize, GEMM_SMEM);
    cudaFuncSetAttribute(attn_flash_kernel,
        cudaFuncAttributeMaxDynamicSharedMemorySize, ATTN_SMEM);

    const int n4 = ROWS * CC / 4;

    // converts
    cvt_f16_kernel<<<(n4 + 255) / 256, 256>>>(x, (__half*)pxh, n4);
    cvt_f16_kernel<<<(MM*CC/4 + 255) / 256, 256>>>(mem, (__half*)pmh, MM*CC/4);
    transpose_cvt_kernel<<<dim3(C3/32, CC/32), dim3(32, 8)>>>(
        W_qkv, (__half*)pwqh, CC, C3);
    transpose_split_kernel<<<dim3(CC/32, CC/32), dim3(32, 8)>>>(
        W_proj, (__nv_bfloat16*)pwph, (__nv_bfloat16*)pwpl, CC, CC);

    // QKV = x @ W_qkv + b_qkv (fp16 single-pass)
    mma_gemm_f16_kernel<<<dim3(C3/128, ROWS/128), 256, GEMM_SMEM>>>(
        (const __half*)pxh, (const __half*)pwqh, b_qkv, (__half*)pqh, C3, CC);

    // attention (+gate) -> g_y fp32
    attn_flash_kernel<<<dim3(TT/64, HH, BB), 128, ATTN_SMEM>>>(
        (const __half*)pqh, (const __half*)pmh, gate, (float*)py);

    // split y -> bf16 hi/lo
    split_kernel<<<(n4 + 255) / 256, 256>>>((const float*)py,
        (__nv_bfloat16*)pyh, (__nv_bfloat16*)pyl, n4);

    // out = y @ W_proj + b_proj (bf16 3-term split)
    mma_gemm_kernel<<<dim3(CC/128, ROWS/128), 256, GEMM_SMEM>>>(
        (const __nv_bfloat16*)pyh, (const __nv_bfloat16*)pyl,
        (const __nv_bfloat16*)pwph, (const __nv_bfloat16*)pwpl,
        b_proj, out, CC, CC);
}

// round 6
// speedup vs baseline: 7.8879x; 1.3553x over previous
#include <cuda_runtime.h>
#include <cuda_bf16.h>
#include <cuda_fp16.h>
#include <cstdint>

// Problem constants
#define BB   128
#define TT   256
#define CC   384
#define HH   6
#define DD   64
#define MM   128
#define WIN  64
#define C3   (3*CC)      // 1152
#define ROWS (BB*TT)     // 32768

// Scratch (allocation-free rule: __device__ globals)
__device__ __half g_qkv_h[ROWS * C3];   // fp16 qkv
__device__ __half g_yh[ROWS * CC];      // attention output fp16 (pre-gate; gate folded into W')
__device__ __half g_xh[ROWS * CC];      // x fp16
__device__ __half g_wqt_h[C3 * CC];     // W_qkv^T fp16 [1152,384]
__device__ __half g_wpt_h[CC * CC];     // (diag(gate) W_proj)^T fp16 [384,384]
__device__ __half g_mem_h[MM * CC];     // memory fp16

// ---------- mma helpers (generic sm_80+ path; compiles on .target sm_103) ----------
__device__ __forceinline__ uint32_t smem_u32(const void* p) {
    uint32_t a;
    asm("{ .reg .u64 t; cvta.to.shared.u64 t, %1; cvt.u32.u64 %0, t; }" : "=r"(a) : "l"(p));
    return a;
}
__device__ __forceinline__ void ldsm_x4(uint32_t addr, uint32_t& r0, uint32_t& r1,
                                        uint32_t& r2, uint32_t& r3) {
    asm volatile("ldmatrix.sync.aligned.m8n8.x4.shared.b16 {%0,%1,%2,%3}, [%4];"
        : "=r"(r0), "=r"(r1), "=r"(r2), "=r"(r3) : "r"(addr));
}
__device__ __forceinline__ void ldsm_x4t(uint32_t addr, uint32_t& r0, uint32_t& r1,
                                         uint32_t& r2, uint32_t& r3) {
    asm volatile("ldmatrix.sync.aligned.m8n8.x4.trans.shared.b16 {%0,%1,%2,%3}, [%4];"
        : "=r"(r0), "=r"(r1), "=r"(r2), "=r"(r3) : "r"(addr));
}
__device__ __forceinline__ void mma_f16(float* d, const uint32_t* a, const uint32_t* b) {
    asm volatile("mma.sync.aligned.m16n8k16.row.col.f32.f16.f16.f32 "
        "{%0,%1,%2,%3}, {%4,%5,%6,%7}, {%8,%9}, {%0,%1,%2,%3};"
        : "+f"(d[0]), "+f"(d[1]), "+f"(d[2]), "+f"(d[3])
        : "r"(a[0]), "r"(a[1]), "r"(a[2]), "r"(a[3]), "r"(b[0]), "r"(b[1]));
}
__device__ __forceinline__ void cp_async16(uint32_t dst, const void* src) {
    asm volatile("cp.async.cg.shared.global [%0], [%1], 16;" :: "r"(dst), "l"(src));
}
#define CP_COMMIT()  asm volatile("cp.async.commit_group;" ::: "memory")
#define CP_WAIT(n)   asm volatile("cp.async.wait_group %0;" :: "n"(n) : "memory")
#define SWZ(r, gb)   ((uint32_t)((r) * 128 + (((gb)) ^ (((r) & 7) << 4))))

// ============================================================
// converts
// ============================================================
__global__ __launch_bounds__(256) void cvt_f16_kernel(
    const float* __restrict__ in, __half* __restrict__ out, int n4)
{
    int i = blockIdx.x * blockDim.x + threadIdx.x;
    if (i >= n4) return;
    float4 v = ((const float4*)in)[i];
    ((__half2*)out)[i*2+0] = __floats2half2_rn(v.x, v.y);
    ((__half2*)out)[i*2+1] = __floats2half2_rn(v.z, v.w);
}

// W[K][N] f32 -> out[N][K] fp16, optionally scaling row k by gate[k]
__global__ __launch_bounds__(256) void transpose_cvt_kernel(
    const float* __restrict__ W, const float* __restrict__ gate,
    __half* __restrict__ out, int K, int N)
{
    __shared__ float t[32][33];
    const int k0 = blockIdx.y * 32, n0 = blockIdx.x * 32;
    const int tx = threadIdx.x, ty = threadIdx.y;   // 32 x 8
    #pragma unroll
    for (int i = ty; i < 32; i += 8)
        t[i][tx] = W[(size_t)(k0 + i) * N + n0 + tx];
    __syncthreads();
    const float g = gate ? gate[k0 + tx] : 1.0f;
    #pragma unroll
    for (int i = ty; i < 32; i += 8)
        out[(size_t)(n0 + i) * K + k0 + tx] = __float2half(t[tx][i] * g);
}

// ============================================================
// fp16 GEMM: C[M,N] = A@B^T + bias ; fp16 in, fp32 acc, OutT out.
// CTA 128x128, BK=64, 8 warps (32x64 each), cp.async double-buffer.
// ============================================================
#define BK 64
#define ATILE 16384
#define GEMM_SMEM (4 * 16384)

template <typename OutT>
__global__ __launch_bounds__(256) void mma_gemm_f16_kernel(
    const __half* __restrict__ A, const __half* __restrict__ B,
    const float* __restrict__ bias, OutT* __restrict__ C, int N, int K)
{
    extern __shared__ __align__(1024) char smem[];
    const uint32_t sb = smem_u32(smem);
    const int tid = threadIdx.x;
    const int wid = tid >> 5, lane = tid & 31;
    const int wm = wid & 3, wn = wid >> 2;
    const int m0 = blockIdx.y * 128, n0 = blockIdx.x * 128;
    const int NCH = K / BK;

    uint32_t st_off[4];
    int ld_r[4];
    #pragma unroll
    for (int i = 0; i < 4; ++i) {
        const int u = tid + i * 256;
        const int r = u >> 3, g = u & 7;
        ld_r[i] = r;
        st_off[i] = SWZ(r, g * 16);
    }

    const int arow0 = wm * 32 + (lane & 15);
    const uint32_t a_kx = (uint32_t)((lane >> 4) * 16);
    const int brow0 = wn * 64 + ((lane >> 4) & 1) * 8 + (lane & 7);
    const uint32_t b_kx = (uint32_t)(((lane >> 3) & 1) * 16);

    float acc[2][8][4];
    #pragma unroll
    for (int a = 0; a < 2; ++a)
        #pragma unroll
        for (int b = 0; b < 8; ++b)
            #pragma unroll
            for (int c = 0; c < 4; ++c) acc[a][b][c] = 0.f;

    #pragma unroll
    for (int i = 0; i < 4; ++i) {
        const int r = ld_r[i], g = (tid + i*256) & 7;
        cp_async16(sb + st_off[i],         A + (size_t)(m0 + r) * K + g * 8);
        cp_async16(sb + ATILE + st_off[i], B + (size_t)(n0 + r) * K + g * 8);
    }
    CP_COMMIT();

    for (int c = 0; c < NCH; ++c) {
        const uint32_t buf = (uint32_t)(c & 1) * (2 * ATILE);
        if (c + 1 < NCH) {
            const int kc = (c + 1) * BK;
            const uint32_t nbuf = (uint32_t)((c + 1) & 1) * (2 * ATILE);
            #pragma unroll
            for (int i = 0; i < 4; ++i) {
                const int r = ld_r[i], g = (tid + i*256) & 7;
                cp_async16(sb + nbuf + st_off[i],         A + (size_t)(m0 + r) * K + kc + g * 8);
                cp_async16(sb + nbuf + ATILE + st_off[i], B + (size_t)(n0 + r) * K + kc + g * 8);
            }
            CP_COMMIT();
            CP_WAIT(1);
        } else {
            CP_WAIT(0);
        }
        __syncthreads();

        const uint32_t abase = sb + buf;
        const uint32_t bbase = sb + buf + ATILE;
        #pragma unroll
        for (int ks = 0; ks < 4; ++ks) {
            const uint32_t ksb = (uint32_t)(ks * 32);
            uint32_t af[2][4];
            #pragma unroll
            for (int mt = 0; mt < 2; ++mt) {
                const int r = arow0 + mt * 16;
                ldsm_x4(abase + SWZ(r, ksb + a_kx), af[mt][0], af[mt][1], af[mt][2], af[mt][3]);
            }
            #pragma unroll
            for (int np = 0; np < 4; ++np) {
                uint32_t bf[4];
                const int r = brow0 + np * 16;
                ldsm_x4(bbase + SWZ(r, ksb + b_kx), bf[0], bf[1], bf[2], bf[3]);
                #pragma unroll
                for (int mt = 0; mt < 2; ++mt) {
                    mma_f16(acc[mt][np*2+0], af[mt], &bf[0]);
                    mma_f16(acc[mt][np*2+1], af[mt], &bf[2]);
                }
            }
        }
        __syncthreads();
    }

    #pragma unroll
    for (int mt = 0; mt < 2; ++mt) {
        const int mrow = m0 + wm * 32 + mt * 16 + (lane >> 2);
        #pragma unroll
        for (int nt = 0; nt < 8; ++nt) {
            const int col = n0 + wn * 64 + nt * 8 + (lane & 3) * 2;
            const float b0 = bias[col], b1 = bias[col + 1];
            if (sizeof(OutT) == 2) {
                *(__half2*)&((__half*)C)[(size_t)mrow * N + col] =
                    __floats2half2_rn(acc[mt][nt][0] + b0, acc[mt][nt][1] + b1);
                *(__half2*)&((__half*)C)[(size_t)(mrow + 8) * N + col] =
                    __floats2half2_rn(acc[mt][nt][2] + b0, acc[mt][nt][3] + b1);
            } else {
                *(float2*)&((float*)C)[(size_t)mrow * N + col] =
                    make_float2(acc[mt][nt][0] + b0, acc[mt][nt][1] + b1);
                *(float2*)&((float*)C)[(size_t)(mrow + 8) * N + col] =
                    make_float2(acc[mt][nt][2] + b0, acc[mt][nt][3] + b1);
            }
        }
    }
}

// ============================================================
// Flash-style HMMA attention -> fp16 y (gate folded into proj weights).
// Block = (q-tile 64, head, batch), 128 threads = 4 warps.
// Keys 0-127 = memory prefix (V==K there), 128-255 = self window qs-64..qs+63.
// smem: Q 8KB | K 32KB | Vself 16KB = 56KB (4 CTAs/SM).
// ============================================================
#define QS_OFF 0
#define KS_OFF 8192
#define VS_OFF 40960
#define ATTN_SMEM 57344

__global__ __launch_bounds__(128) void attn_flash_kernel(
    const __half* __restrict__ qkv, const __half* __restrict__ memh,
    __half* __restrict__ y)
{
    extern __shared__ __align__(1024) char smem[];
    const uint32_t sb = smem_u32(smem);
    const int qt = blockIdx.x, h = blockIdx.y, b = blockIdx.z;
    const int qs = qt * 64;
    const int tid = threadIdx.x;
    const int wid = tid >> 5, lane = tid & 31;

    // ---- stage Q (64 rows), K (256 rows), V self (128 rows) ----
    #pragma unroll
    for (int i = 0; i < 4; ++i) {
        const int u = tid + i * 128;
        const int r = u >> 3, g = u & 7;
        cp_async16(sb + QS_OFF + SWZ(r, g * 16),
                   qkv + (size_t)(b*TT + qs + r) * C3 + h*DD + g*8);
    }
    #pragma unroll
    for (int i = 0; i < 16; ++i) {
        const int u = tid + i * 128;
        const int r = u >> 3, g = u & 7;
        if (r < MM) {
            cp_async16(sb + KS_OFF + SWZ(r, g * 16), memh + (size_t)r * CC + h*DD + g*8);
        } else {
            const int p = qs - 64 + (r - MM);
            const int vr = r - MM;
            if (p >= 0) {
                cp_async16(sb + KS_OFF + SWZ(r, g * 16),
                           qkv + (size_t)(b*TT + p) * C3 + CC + h*DD + g*8);
                cp_async16(sb + VS_OFF + SWZ(vr, g * 16),
                           qkv + (size_t)(b*TT + p) * C3 + 2*CC + h*DD + g*8);
            } else {
                const uint4 z = make_uint4(0,0,0,0);
                *(uint4*)(smem + KS_OFF + SWZ(r, g * 16)) = z;
                *(uint4*)(smem + VS_OFF + SWZ(vr, g * 16)) = z;
            }
        }
    }
    CP_COMMIT();
    CP_WAIT(0);
    __syncthreads();

    const int qb = wid * 16;
    const int r_lo = lane >> 2;
    const int c_lo = (lane & 3) * 2;
    const int qi0 = qs + qb + r_lo;
    const int qi1 = qi0 + 8;

    const uint32_t a_kx = (uint32_t)((lane >> 4) * 16);
    const int arow = qb + (lane & 15);
    const int brow_base = ((lane >> 4) & 1) * 8 + (lane & 7);
    const uint32_t b_kx = (uint32_t)(((lane >> 3) & 1) * 16);
    const int vrow_base = ((lane >> 3) & 1) * 8 + (lane & 7);
    const uint32_t v_nx = (uint32_t)((lane >> 4) * 16);

    float O[8][4];
    #pragma unroll
    for (int t = 0; t < 8; ++t)
        #pragma unroll
        for (int e = 0; e < 4; ++e) O[t][e] = 0.f;
    float m0 = -1e30f, m1 = -1e30f, l0 = 0.f, l1 = 0.f;

    for (int c = 0; c < 4; ++c) {
        if (qt == 0 && c == 2) continue;   // self keys p in [-64,-1]: fully masked
        const int kb = c * 64;

        // ---- S = Q K^T ----
        float s[8][4];
        #pragma unroll
        for (int t = 0; t < 8; ++t)
            #pragma unroll
            for (int e = 0; e < 4; ++e) s[t][e] = 0.f;
        #pragma unroll
        for (int ks = 0; ks < 4; ++ks) {
            const uint32_t ksb = (uint32_t)(ks * 32);
            uint32_t af[4];
            ldsm_x4(sb + QS_OFF + SWZ(arow, ksb + a_kx), af[0], af[1], af[2], af[3]);
            #pragma unroll
            for (int np = 0; np < 4; ++np) {
                uint32_t bf[4];
                const int r = kb + np * 16 + brow_base;
                ldsm_x4(sb + KS_OFF + SWZ(r, ksb + b_kx), bf[0], bf[1], bf[2], bf[3]);
                mma_f16(s[np*2+0], af, &bf[0]);
                mma_f16(s[np*2+1], af, &bf[2]);
            }
        }

        // ---- scale + mask ----
        #pragma unroll
        for (int t = 0; t < 8; ++t) {
            #pragma unroll
            for (int e = 0; e < 4; ++e) {
                const int key = kb + t*8 + c_lo + (e & 1);
                const int qi = (e < 2) ? qi0 : qi1;
                bool valid = true;
                if (key >= MM) {
                    const int p = qs - 64 + (key - MM);
                    valid = (p >= 0) && (p <= qi) && (qi - p <= WIN);
                }
                s[t][e] = valid ? s[t][e] * 0.125f : -1e30f;
            }
        }

        // ---- online softmax ----
        float cm0 = -1e30f, cm1 = -1e30f;
        #pragma unroll
        for (int t = 0; t < 8; ++t) {
            cm0 = fmaxf(cm0, fmaxf(s[t][0], s[t][1]));
            cm1 = fmaxf(cm1, fmaxf(s[t][2], s[t][3]));
        }
        cm0 = fmaxf(cm0, __shfl_xor_sync(0xFFFFFFFFu, cm0, 1));
        cm0 = fmaxf(cm0, __shfl_xor_sync(0xFFFFFFFFu, cm0, 2));
        cm1 = fmaxf(cm1, __shfl_xor_sync(0xFFFFFFFFu, cm1, 1));
        cm1 = fmaxf(cm1, __shfl_xor_sync(0xFFFFFFFFu, cm1, 2));
        const float mn0 = fmaxf(m0, cm0), mn1 = fmaxf(m1, cm1);
        const float sc0 = __expf(m0 - mn0), sc1 = __expf(m1 - mn1);
        m0 = mn0; m1 = mn1;
        l0 *= sc0; l1 *= sc1;
        #pragma unroll
        for (int t = 0; t < 8; ++t) {
            O[t][0] *= sc0; O[t][1] *= sc0;
            O[t][2] *= sc1; O[t][3] *= sc1;
        }
        uint32_t ph[8][2];
        #pragma unroll
        for (int t = 0; t < 8; ++t) {
            const float p0 = __expf(s[t][0] - mn0), p1 = __expf(s[t][1] - mn0);
            const float p2 = __expf(s[t][2] - mn1), p3 = __expf(s[t][3] - mn1);
            l0 += p0 + p1; l1 += p2 + p3;
            __half2 h01 = __floats2half2_rn(p0, p1);
            __half2 h23 = __floats2half2_rn(p2, p3);
            ph[t][0] = *(uint32_t*)&h01;
            ph[t][1] = *(uint32_t*)&h23;
        }

        // ---- O += P V  (mem prefix: V rows live in the K buffer) ----
        #pragma unroll
        for (int ks = 0; ks < 4; ++ks) {
            uint32_t a[4] = { ph[2*ks][0], ph[2*ks][1], ph[2*ks+1][0], ph[2*ks+1][1] };
            const int rv = kb + ks * 16 + vrow_base;
            const uint32_t vbase = (kb < MM) ? (sb + KS_OFF + (uint32_t)(rv) * 0u)
                                             : 0u; // placeholder (computed below)
            #pragma unroll
            for (int g = 0; g < 4; ++g) {
                uint32_t vb[4];
                uint32_t addr;
                if (kb < MM)
                    addr = sb + KS_OFF + SWZ(rv, (uint32_t)(g * 32) + v_nx);
                else
                    addr = sb + VS_OFF + SWZ(rv - MM, (uint32_t)(g * 32) + v_nx);
                ldsm_x4t(addr, vb[0], vb[1], vb[2], vb[3]);
                mma_f16(O[g*2+0], a, &vb[0]);
                mma_f16(O[g*2+1], a, &vb[2]);
            }
            (void)vbase;
        }
    }

    // ---- finalize: write fp16 y ----
    l0 += __shfl_xor_sync(0xFFFFFFFFu, l0, 1);
    l0 += __shfl_xor_sync(0xFFFFFFFFu, l0, 2);
    l1 += __shfl_xor_sync(0xFFFFFFFFu, l1, 1);
    l1 += __shfl_xor_sync(0xFFFFFFFFu, l1, 2);
    const float rc0 = 1.0f / l0, rc1 = 1.0f / l1;

    const size_t row0 = (size_t)(b*TT + qs + qb + r_lo);
    #pragma unroll
    for (int t = 0; t < 8; ++t) {
        const int col = h*DD + t*8 + c_lo;
        *(__half2*)&y[row0 * CC + col] =
            __floats2half2_rn(O[t][0] * rc0, O[t][1] * rc0);
        *(__half2*)&y[(row0 + 8) * CC + col] =
            __floats2half2_rn(O[t][2] * rc1, O[t][3] * rc1);
    }
}

// ============================================================
extern "C" void kernel_launch(void* const* d_in, const int* in_sizes, int n_in,
                              void* d_out, int out_size)
{
    const float* x      = (const float*)d_in[0];
    const float* mem    = (const float*)d_in[1];
    const float* W_qkv  = (const float*)d_in[2];
    const float* b_qkv  = (const float*)d_in[3];
    const float* W_proj = (const float*)d_in[4];
    const float* b_proj = (const float*)d_in[5];
    const float* gate   = (const float*)d_in[6];
    float* out = (float*)d_out;

    void *pqh, *pyh, *pxh, *pwqh, *pwph, *pmh;
    cudaGetSymbolAddress(&pqh, g_qkv_h);
    cudaGetSymbolAddress(&pyh, g_yh);
    cudaGetSymbolAddress(&pxh, g_xh);
    cudaGetSymbolAddress(&pwqh, g_wqt_h);
    cudaGetSymbolAddress(&pwph, g_wpt_h);
    cudaGetSymbolAddress(&pmh, g_mem_h);

    cudaFuncSetAttribute(mma_gemm_f16_kernel<__half>,
        cudaFuncAttributeMaxDynamicSharedMemorySize, GEMM_SMEM);
    cudaFuncSetAttribute(mma_gemm_f16_kernel<float>,
        cudaFuncAttributeMaxDynamicSharedMemorySize, GEMM_SMEM);
    cudaFuncSetAttribute(attn_flash_kernel,
        cudaFuncAttributeMaxDynamicSharedMemorySize, ATTN_SMEM);

    const int n4 = ROWS * CC / 4;

    // converts
    cvt_f16_kernel<<<(n4 + 255) / 256, 256>>>(x, (__half*)pxh, n4);
    cvt_f16_kernel<<<(MM*CC/4 + 255) / 256, 256>>>(mem, (__half*)pmh, MM*CC/4);
    transpose_cvt_kernel<<<dim3(C3/32, CC/32), dim3(32, 8)>>>(
        W_qkv, nullptr, (__half*)pwqh, CC, C3);
    transpose_cvt_kernel<<<dim3(CC/32, CC/32), dim3(32, 8)>>>(
        W_proj, gate, (__half*)pwph, CC, CC);   // gate folded into W_proj rows

    // QKV = x @ W_qkv + b_qkv (fp16 -> fp16)
    mma_gemm_f16_kernel<__half><<<dim3(C3/128, ROWS/128), 256, GEMM_SMEM>>>(
        (const __half*)pxh, (const __half*)pwqh, b_qkv, (__half*)pqh, C3, CC);

    // attention -> y fp16 (pre-gate)
    attn_flash_kernel<<<dim3(TT/64, HH, BB), 128, ATTN_SMEM>>>(
        (const __half*)pqh, (const __half*)pmh, (__half*)pyh);

    // out = y @ (gate.W_proj) + b_proj (fp16 -> fp32)
    mma_gemm_f16_kernel<float><<<dim3(CC/128, ROWS/128), 256, GEMM_SMEM>>>(
        (const __half*)pyh, (const __half*)pwph, b_proj, out, CC, CC);
}

// round 8
// speedup vs baseline: 8.3136x; 1.0540x over previous
#include <cuda_runtime.h>
#include <cuda_bf16.h>
#include <cuda_fp16.h>
#include <cstdint>

// Problem constants
#define BB   128
#define TT   256
#define CC   384
#define HH   6
#define DD   64
#define MM   128
#define WIN  64
#define C3   (3*CC)      // 1152
#define ROWS (BB*TT)     // 32768

// Scratch (allocation-free rule: __device__ globals)
__device__ __half g_qkv_h[ROWS * C3];   // fp16 qkv
__device__ __half g_yh[ROWS * CC];      // attention output fp16 (pre-gate)
__device__ __half g_xh[ROWS * CC];      // x fp16
__device__ __half g_wqt_h[C3 * CC];     // W_qkv^T fp16 [1152,384]
__device__ __half g_wpt_h[CC * CC];     // (diag(gate) W_proj)^T fp16 [384,384]
__device__ __half g_mem_h[MM * CC];     // memory fp16

// ---------- mma helpers (generic sm_80+ path; compiles on .target sm_103) ----------
__device__ __forceinline__ uint32_t smem_u32(const void* p) {
    uint32_t a;
    asm("{ .reg .u64 t; cvta.to.shared.u64 t, %1; cvt.u32.u64 %0, t; }" : "=r"(a) : "l"(p));
    return a;
}
__device__ __forceinline__ void ldsm_x4(uint32_t addr, uint32_t& r0, uint32_t& r1,
                                        uint32_t& r2, uint32_t& r3) {
    asm volatile("ldmatrix.sync.aligned.m8n8.x4.shared.b16 {%0,%1,%2,%3}, [%4];"
        : "=r"(r0), "=r"(r1), "=r"(r2), "=r"(r3) : "r"(addr));
}
__device__ __forceinline__ void ldsm_x4t(uint32_t addr, uint32_t& r0, uint32_t& r1,
                                         uint32_t& r2, uint32_t& r3) {
    asm volatile("ldmatrix.sync.aligned.m8n8.x4.trans.shared.b16 {%0,%1,%2,%3}, [%4];"
        : "=r"(r0), "=r"(r1), "=r"(r2), "=r"(r3) : "r"(addr));
}
__device__ __forceinline__ void mma_f16(float* d, const uint32_t* a, const uint32_t* b) {
    asm volatile("mma.sync.aligned.m16n8k16.row.col.f32.f16.f16.f32 "
        "{%0,%1,%2,%3}, {%4,%5,%6,%7}, {%8,%9}, {%0,%1,%2,%3};"
        : "+f"(d[0]), "+f"(d[1]), "+f"(d[2]), "+f"(d[3])
        : "r"(a[0]), "r"(a[1]), "r"(a[2]), "r"(a[3]), "r"(b[0]), "r"(b[1]));
}
__device__ __forceinline__ void cp_async16(uint32_t dst, const void* src) {
    asm volatile("cp.async.cg.shared.global [%0], [%1], 16;" :: "r"(dst), "l"(src));
}
#define CP_COMMIT()  asm volatile("cp.async.commit_group;" ::: "memory")
#define CP_WAIT(n)   asm volatile("cp.async.wait_group %0;" :: "n"(n) : "memory")
#define SWZ(r, gb)   ((uint32_t)((r) * 128 + (((gb)) ^ (((r) & 7) << 4))))

// log2(e) * (1/sqrt(64)) : softmax runs in exp2 domain
#define SCALE_LOG2E 0.18033688f

// ============================================================
// Fused prep kernel: cvt x, cvt mem, transpose W_qkv, transpose+gate W_proj
// ============================================================
#define PREP_X_BLK   (ROWS * CC / 4 / 256)        // 12288
#define PREP_MEM_BLK (MM * CC / 4 / 256)          // 48
#define PREP_WQ_BLK  ((C3/32) * (CC/32))          // 432
#define PREP_WP_BLK  ((CC/32) * (CC/32))          // 144
#define PREP_GRID    (PREP_X_BLK + PREP_MEM_BLK + PREP_WQ_BLK + PREP_WP_BLK)

__global__ __launch_bounds__(256) void prep_kernel(
    const float* __restrict__ x, const float* __restrict__ mem,
    const float* __restrict__ Wq, const float* __restrict__ Wp,
    const float* __restrict__ gate,
    __half* __restrict__ xh, __half* __restrict__ memh,
    __half* __restrict__ wqt, __half* __restrict__ wpt)
{
    __shared__ float t[32][33];
    const int bid = blockIdx.x;
    const int tid = threadIdx.x;

    if (bid < PREP_X_BLK) {
        const int i = bid * 256 + tid;
        float4 v = ((const float4*)x)[i];
        ((__half2*)xh)[i*2+0] = __floats2half2_rn(v.x, v.y);
        ((__half2*)xh)[i*2+1] = __floats2half2_rn(v.z, v.w);
    } else if (bid < PREP_X_BLK + PREP_MEM_BLK) {
        const int i = (bid - PREP_X_BLK) * 256 + tid;
        float4 v = ((const float4*)mem)[i];
        ((__half2*)memh)[i*2+0] = __floats2half2_rn(v.x, v.y);
        ((__half2*)memh)[i*2+1] = __floats2half2_rn(v.z, v.w);
    } else {
        const float* W;
        __half* out;
        int n0, k0, N_;
        bool use_gate;
        if (bid < PREP_X_BLK + PREP_MEM_BLK + PREP_WQ_BLK) {
            const int tb = bid - (PREP_X_BLK + PREP_MEM_BLK);
            W = Wq; out = wqt; N_ = C3; use_gate = false;
            n0 = (tb % (C3/32)) * 32;
            k0 = (tb / (C3/32)) * 32;
        } else {
            const int tb = bid - (PREP_X_BLK + PREP_MEM_BLK + PREP_WQ_BLK);
            W = Wp; out = wpt; N_ = CC; use_gate = true;
            n0 = (tb % (CC/32)) * 32;
            k0 = (tb / (CC/32)) * 32;
        }
        const int tx = tid & 31, ty = tid >> 5;   // 32 x 8
        #pragma unroll
        for (int i = ty; i < 32; i += 8)
            t[i][tx] = W[(size_t)(k0 + i) * N_ + n0 + tx];
        __syncthreads();
        const float g = use_gate ? gate[k0 + tx] : 1.0f;
        #pragma unroll
        for (int i = ty; i < 32; i += 8)
            out[(size_t)(n0 + i) * CC + k0 + tx] = __float2half(t[tx][i] * g);
    }
}

// ============================================================
// fp16 GEMM: C[M,N] = A@B^T + bias ; K = CC = 384 compile-time.
// CTA 128x128, BK=64, 8 warps (32x64 each), cp.async double-buffer.
// ============================================================
#define BK 64
#define ATILE 16384
#define GEMM_SMEM (4 * 16384)
#define GK CC
#define GNCH (GK / BK)   // 6

template <typename OutT>
__global__ __launch_bounds__(256) void mma_gemm_f16_kernel(
    const __half* __restrict__ A, const __half* __restrict__ B,
    const float* __restrict__ bias, OutT* __restrict__ C, int N)
{
    extern __shared__ __align__(1024) char smem[];
    const uint32_t sb = smem_u32(smem);
    const int tid = threadIdx.x;
    const int wid = tid >> 5, lane = tid & 31;
    const int wm = wid & 3, wn = wid >> 2;
    const int m0 = blockIdx.y * 128, n0 = blockIdx.x * 128;

    uint32_t st_off[4];
    int ld_r[4];
    #pragma unroll
    for (int i = 0; i < 4; ++i) {
        const int u = tid + i * 256;
        const int r = u >> 3, g = u & 7;
        ld_r[i] = r;
        st_off[i] = SWZ(r, g * 16);
    }

    const int arow0 = wm * 32 + (lane & 15);
    const uint32_t a_kx = (uint32_t)((lane >> 4) * 16);
    const int brow0 = wn * 64 + ((lane >> 4) & 1) * 8 + (lane & 7);
    const uint32_t b_kx = (uint32_t)(((lane >> 3) & 1) * 16);

    float acc[2][8][4];
    #pragma unroll
    for (int a = 0; a < 2; ++a)
        #pragma unroll
        for (int b = 0; b < 8; ++b)
            #pragma unroll
            for (int c = 0; c < 4; ++c) acc[a][b][c] = 0.f;

    #pragma unroll
    for (int i = 0; i < 4; ++i) {
        const int r = ld_r[i], g = (tid + i*256) & 7;
        cp_async16(sb + st_off[i],         A + (size_t)(m0 + r) * GK + g * 8);
        cp_async16(sb + ATILE + st_off[i], B + (size_t)(n0 + r) * GK + g * 8);
    }
    CP_COMMIT();

    #pragma unroll
    for (int c = 0; c < GNCH; ++c) {
        const uint32_t buf = (uint32_t)(c & 1) * (2 * ATILE);
        if (c + 1 < GNCH) {
            const int kc = (c + 1) * BK;
            const uint32_t nbuf = (uint32_t)((c + 1) & 1) * (2 * ATILE);
            #pragma unroll
            for (int i = 0; i < 4; ++i) {
                const int r = ld_r[i], g = (tid + i*256) & 7;
                cp_async16(sb + nbuf + st_off[i],         A + (size_t)(m0 + r) * GK + kc + g * 8);
                cp_async16(sb + nbuf + ATILE + st_off[i], B + (size_t)(n0 + r) * GK + kc + g * 8);
            }
            CP_COMMIT();
            CP_WAIT(1);
        } else {
            CP_WAIT(0);
        }
        __syncthreads();

        const uint32_t abase = sb + buf;
        const uint32_t bbase = sb + buf + ATILE;
        #pragma unroll
        for (int ks = 0; ks < 4; ++ks) {
            const uint32_t ksb = (uint32_t)(ks * 32);
            uint32_t af[2][4];
            #pragma unroll
            for (int mt = 0; mt < 2; ++mt) {
                const int r = arow0 + mt * 16;
                ldsm_x4(abase + SWZ(r, ksb + a_kx), af[mt][0], af[mt][1], af[mt][2], af[mt][3]);
            }
            #pragma unroll
            for (int np = 0; np < 4; ++np) {
                uint32_t bf[4];
                const int r = brow0 + np * 16;
                ldsm_x4(bbase + SWZ(r, ksb + b_kx), bf[0], bf[1], bf[2], bf[3]);
                #pragma unroll
                for (int mt = 0; mt < 2; ++mt) {
                    mma_f16(acc[mt][np*2+0], af[mt], &bf[0]);
                    mma_f16(acc[mt][np*2+1], af[mt], &bf[2]);
                }
            }
        }
        __syncthreads();
    }

    #pragma unroll
    for (int mt = 0; mt < 2; ++mt) {
        const int mrow = m0 + wm * 32 + mt * 16 + (lane >> 2);
        #pragma unroll
        for (int nt = 0; nt < 8; ++nt) {
            const int col = n0 + wn * 64 + nt * 8 + (lane & 3) * 2;
            const float b0 = bias[col], b1 = bias[col + 1];
            if (sizeof(OutT) == 2) {
                *(__half2*)&((__half*)C)[(size_t)mrow * N + col] =
                    __floats2half2_rn(acc[mt][nt][0] + b0, acc[mt][nt][1] + b1);
                *(__half2*)&((__half*)C)[(size_t)(mrow + 8) * N + col] =
                    __floats2half2_rn(acc[mt][nt][2] + b0, acc[mt][nt][3] + b1);
            } else {
                *(float2*)&((float*)C)[(size_t)mrow * N + col] =
                    make_float2(acc[mt][nt][0] + b0, acc[mt][nt][1] + b1);
                *(float2*)&((float*)C)[(size_t)(mrow + 8) * N + col] =
                    make_float2(acc[mt][nt][2] + b0, acc[mt][nt][3] + b1);
            }
        }
    }
}

// ============================================================
// Flash-style HMMA attention -> fp16 y.
// Block = (q-tile 64, head, batch), 128 threads = 4 warps.
// Keys 0-127 = memory prefix (V==K there), 128-255 = self window qs-64..qs+63.
// Warp w owns q rows 16w..16w+15. Fully-masked 16-key tiles are skipped:
//   chunk 2 (keys qs-64..qs-1): tile np valid iff np >= w (window)
//   chunk 3 (keys qs..qs+63):   tile np valid iff np <= w (causal)
// Softmax runs in exp2 domain (scale pre-multiplied by log2 e).
// ============================================================
#define QS_OFF 0
#define KS_OFF 8192
#define VS_OFF 40960
#define ATTN_SMEM 57344

__global__ __launch_bounds__(128) void attn_flash_kernel(
    const __half* __restrict__ qkv, const __half* __restrict__ memh,
    __half* __restrict__ y)
{
    extern __shared__ __align__(1024) char smem[];
    const uint32_t sb = smem_u32(smem);
    const int qt = blockIdx.x, h = blockIdx.y, b = blockIdx.z;
    const int qs = qt * 64;
    const int tid = threadIdx.x;
    const int wid = tid >> 5, lane = tid & 31;

    // ---- stage Q (64 rows), K (256 rows), V self (128 rows) ----
    #pragma unroll
    for (int i = 0; i < 4; ++i) {
        const int u = tid + i * 128;
        const int r = u >> 3, g = u & 7;
        cp_async16(sb + QS_OFF + SWZ(r, g * 16),
                   qkv + (size_t)(b*TT + qs + r) * C3 + h*DD + g*8);
    }
    #pragma unroll
    for (int i = 0; i < 16; ++i) {
        const int u = tid + i * 128;
        const int r = u >> 3, g = u & 7;
        if (r < MM) {
            cp_async16(sb + KS_OFF + SWZ(r, g * 16), memh + (size_t)r * CC + h*DD + g*8);
        } else {
            const int p = qs - 64 + (r - MM);
            const int vr = r - MM;
            if (p >= 0) {
                cp_async16(sb + KS_OFF + SWZ(r, g * 16),
                           qkv + (size_t)(b*TT + p) * C3 + CC + h*DD + g*8);
                cp_async16(sb + VS_OFF + SWZ(vr, g * 16),
                           qkv + (size_t)(b*TT + p) * C3 + 2*CC + h*DD + g*8);
            } else {
                const uint4 z = make_uint4(0,0,0,0);
                *(uint4*)(smem + KS_OFF + SWZ(r, g * 16)) = z;
                *(uint4*)(smem + VS_OFF + SWZ(vr, g * 16)) = z;
            }
        }
    }
    CP_COMMIT();
    CP_WAIT(0);
    __syncthreads();

    const int qb = wid * 16;
    const int r_lo = lane >> 2;
    const int c_lo = (lane & 3) * 2;
    const int qi0 = qs + qb + r_lo;
    const int qi1 = qi0 + 8;

    const uint32_t a_kx = (uint32_t)((lane >> 4) * 16);
    const int arow = qb + (lane & 15);
    const int brow_base = ((lane >> 4) & 1) * 8 + (lane & 7);
    const uint32_t b_kx = (uint32_t)(((lane >> 3) & 1) * 16);
    const int vrow_base = ((lane >> 3) & 1) * 8 + (lane & 7);
    const uint32_t v_nx = (uint32_t)((lane >> 4) * 16);

    float O[8][4];
    #pragma unroll
    for (int t = 0; t < 8; ++t)
        #pragma unroll
        for (int e = 0; e < 4; ++e) O[t][e] = 0.f;
    float m0 = -1e30f, m1 = -1e30f, l0 = 0.f, l1 = 0.f;

    #pragma unroll
    for (int c = 0; c < 4; ++c) {
        if (qt == 0 && c == 2) continue;   // self keys p in [-64,-1]: fully masked
        const int kb = c * 64;

        // ---- S = Q K^T (skip fully-masked 16-key tiles) ----
        float s[8][4];
        #pragma unroll
        for (int t = 0; t < 8; ++t)
            #pragma unroll
            for (int e = 0; e < 4; ++e) s[t][e] = 0.f;
        #pragma unroll
        for (int ks = 0; ks < 4; ++ks) {
            const uint32_t ksb = (uint32_t)(ks * 32);
            uint32_t af[4];
            ldsm_x4(sb + QS_OFF + SWZ(arow, ksb + a_kx), af[0], af[1], af[2], af[3]);
            #pragma unroll
            for (int np = 0; np < 4; ++np) {
                if (c == 2 && np < wid) continue;
                if (c == 3 && np > wid) continue;
                uint32_t bf[4];
                const int r = kb + np * 16 + brow_base;
                ldsm_x4(sb + KS_OFF + SWZ(r, ksb + b_kx), bf[0], bf[1], bf[2], bf[3]);
                mma_f16(s[np*2+0], af, &bf[0]);
                mma_f16(s[np*2+1], af, &bf[2]);
            }
        }

        // ---- scale (exp2 domain) + mask ----
        #pragma unroll
        for (int t = 0; t < 8; ++t) {
            #pragma unroll
            for (int e = 0; e < 4; ++e) {
                const int key = kb + t*8 + c_lo + (e & 1);
                const int qi = (e < 2) ? qi0 : qi1;
                bool valid = true;
                if (key >= MM) {
                    const int p = qs - 64 + (key - MM);
                    valid = (p >= 0) && (p <= qi) && (qi - p <= WIN);
                }
                s[t][e] = valid ? s[t][e] * SCALE_LOG2E : -1e30f;
            }
        }

        // ---- online softmax (exp2 domain) ----
        float cm0 = -1e30f, cm1 = -1e30f;
        #pragma unroll
        for (int t = 0; t < 8; ++t) {
            cm0 = fmaxf(cm0, fmaxf(s[t][0], s[t][1]));
            cm1 = fmaxf(cm1, fmaxf(s[t][2], s[t][3]));
        }
        cm0 = fmaxf(cm0, __shfl_xor_sync(0xFFFFFFFFu, cm0, 1));
        cm0 = fmaxf(cm0, __shfl_xor_sync(0xFFFFFFFFu, cm0, 2));
        cm1 = fmaxf(cm1, __shfl_xor_sync(0xFFFFFFFFu, cm1, 1));
        cm1 = fmaxf(cm1, __shfl_xor_sync(0xFFFFFFFFu, cm1, 2));
        const float mn0 = fmaxf(m0, cm0), mn1 = fmaxf(m1, cm1);
        const float sc0 = exp2f(m0 - mn0), sc1 = exp2f(m1 - mn1);
        m0 = mn0; m1 = mn1;
        l0 *= sc0; l1 *= sc1;
        #pragma unroll
        for (int t = 0; t < 8; ++t) {
            O[t][0] *= sc0; O[t][1] *= sc0;
            O[t][2] *= sc1; O[t][3] *= sc1;
        }
        uint32_t ph[8][2];
        #pragma unroll
        for (int t = 0; t < 8; ++t) {
            const float p0 = exp2f(s[t][0] - mn0), p1 = exp2f(s[t][1] - mn0);
            const float p2 = exp2f(s[t][2] - mn1), p3 = exp2f(s[t][3] - mn1);
            l0 += p0 + p1; l1 += p2 + p3;
            __half2 h01 = __floats2half2_rn(p0, p1);
            __half2 h23 = __floats2half2_rn(p2, p3);
            ph[t][0] = *(uint32_t*)&h01;
            ph[t][1] = *(uint32_t*)&h23;
        }

        // ---- O += P V (mem prefix V rows live in K buffer; skip masked tiles) ----
        #pragma unroll
        for (int ks = 0; ks < 4; ++ks) {
            if (c == 2 && ks < wid) continue;
            if (c == 3 && ks > wid) continue;
            uint32_t a[4] = { ph[2*ks][0], ph[2*ks][1], ph[2*ks+1][0], ph[2*ks+1][1] };
            const int rv = kb + ks * 16 + vrow_base;
            #pragma unroll
            for (int g = 0; g < 4; ++g) {
                uint32_t vb[4];
                uint32_t addr;
                if (kb < MM)
                    addr = sb + KS_OFF + SWZ(rv, (uint32_t)(g * 32) + v_nx);
                else
                    addr = sb + VS_OFF + SWZ(rv - MM, (uint32_t)(g * 32) + v_nx);
                ldsm_x4t(addr, vb[0], vb[1], vb[2], vb[3]);
                mma_f16(O[g*2+0], a, &vb[0]);
                mma_f16(O[g*2+1], a, &vb[2]);
            }
        }
    }

    // ---- finalize: write fp16 y ----
    l0 += __shfl_xor_sync(0xFFFFFFFFu, l0, 1);
    l0 += __shfl_xor_sync(0xFFFFFFFFu, l0, 2);
    l1 += __shfl_xor_sync(0xFFFFFFFFu, l1, 1);
    l1 += __shfl_xor_sync(0xFFFFFFFFu, l1, 2);
    const float rc0 = 1.0f / l0, rc1 = 1.0f / l1;

    const size_t row0 = (size_t)(b*TT + qs + qb + r_lo);
    #pragma unroll
    for (int t = 0; t < 8; ++t) {
        const int col = h*DD + t*8 + c_lo;
        *(__half2*)&y[row0 * CC + col] =
            __floats2half2_rn(O[t][0] * rc0, O[t][1] * rc0);
        *(__half2*)&y[(row0 + 8) * CC + col] =
            __floats2half2_rn(O[t][2] * rc1, O[t][3] * rc1);
    }
}

// ============================================================
extern "C" void kernel_launch(void* const* d_in, const int* in_sizes, int n_in,
                              void* d_out, int out_size)
{
    const float* x      = (const float*)d_in[0];
    const float* mem    = (const float*)d_in[1];
    const float* W_qkv  = (const float*)d_in[2];
    const float* b_qkv  = (const float*)d_in[3];
    const float* W_proj = (const float*)d_in[4];
    const float* b_proj = (const float*)d_in[5];
    const float* gate   = (const float*)d_in[6];
    float* out = (float*)d_out;

    void *pqh, *pyh, *pxh, *pwqh, *pwph, *pmh;
    cudaGetSymbolAddress(&pqh, g_qkv_h);
    cudaGetSymbolAddress(&pyh, g_yh);
    cudaGetSymbolAddress(&pxh, g_xh);
    cudaGetSymbolAddress(&pwqh, g_wqt_h);
    cudaGetSymbolAddress(&pwph, g_wpt_h);
    cudaGetSymbolAddress(&pmh, g_mem_h);

    cudaFuncSetAttribute(mma_gemm_f16_kernel<__half>,
        cudaFuncAttributeMaxDynamicSharedMemorySize, GEMM_SMEM);
    cudaFuncSetAttribute(mma_gemm_f16_kernel<float>,
        cudaFuncAttributeMaxDynamicSharedMemorySize, GEMM_SMEM);
    cudaFuncSetAttribute(attn_flash_kernel,
        cudaFuncAttributeMaxDynamicSharedMemorySize, ATTN_SMEM);

    // fused prep: cvt x, cvt mem, transpose W_qkv, transpose+gate W_proj
    prep_kernel<<<PREP_GRID, 256>>>(x, mem, W_qkv, W_proj, gate,
        (__half*)pxh, (__half*)pmh, (__half*)pwqh, (__half*)pwph);

    // QKV = x @ W_qkv + b_qkv (fp16 -> fp16)
    mma_gemm_f16_kernel<__half><<<dim3(C3/128, ROWS/128), 256, GEMM_SMEM>>>(
        (const __half*)pxh, (const __half*)pwqh, b_qkv, (__half*)pqh, C3);

    // attention -> y fp16 (pre-gate)
    attn_flash_kernel<<<dim3(TT/64, HH, BB), 128, ATTN_SMEM>>>(
        (const __half*)pqh, (const __half*)pmh, (__half*)pyh);

    // out = y @ (gate.W_proj) + b_proj (fp16 -> fp32)
    mma_gemm_f16_kernel<float><<<dim3(CC/128, ROWS/128), 256, GEMM_SMEM>>>(
        (const __half*)pyh, (const __half*)pwph, b_proj, out, CC);
}

// round 11
// speedup vs baseline: 9.2491x; 1.1125x over previous
#include <cuda_runtime.h>
#include <cuda_bf16.h>
#include <cuda_fp16.h>
#include <cstdint>

// Problem constants
#define BB   128
#define TT   256
#define CC   384
#define HH   6
#define DD   64
#define MM   128
#define WIN  64
#define C3   (3*CC)      // 1152
#define ROWS (BB*TT)     // 32768

// Scratch (allocation-free rule: __device__ globals)
__device__ __half g_qkv_h[ROWS * C3];   // fp16 qkv
__device__ __half g_yh[ROWS * CC];      // attention output fp16 (pre-gate)
__device__ __half g_xh[ROWS * CC];      // x fp16
__device__ __half g_wqt_h[C3 * CC];     // W_qkv^T fp16 [1152,384]
__device__ __half g_wpt_h[CC * CC];     // (diag(gate) W_proj)^T fp16 [384,384]
__device__ __half g_mem_h[MM * CC];     // memory fp16

// ---------- mma helpers (generic sm_80+ path; compiles on .target sm_103) ----------
__device__ __forceinline__ uint32_t smem_u32(const void* p) {
    uint32_t a;
    asm("{ .reg .u64 t; cvta.to.shared.u64 t, %1; cvt.u32.u64 %0, t; }" : "=r"(a) : "l"(p));
    return a;
}
__device__ __forceinline__ void ldsm_x4(uint32_t addr, uint32_t& r0, uint32_t& r1,
                                        uint32_t& r2, uint32_t& r3) {
    asm volatile("ldmatrix.sync.aligned.m8n8.x4.shared.b16 {%0,%1,%2,%3}, [%4];"
        : "=r"(r0), "=r"(r1), "=r"(r2), "=r"(r3) : "r"(addr));
}
__device__ __forceinline__ void ldsm_x4t(uint32_t addr, uint32_t& r0, uint32_t& r1,
                                         uint32_t& r2, uint32_t& r3) {
    asm volatile("ldmatrix.sync.aligned.m8n8.x4.trans.shared.b16 {%0,%1,%2,%3}, [%4];"
        : "=r"(r0), "=r"(r1), "=r"(r2), "=r"(r3) : "r"(addr));
}
__device__ __forceinline__ void mma_f16(float* d, const uint32_t* a, const uint32_t* b) {
    asm volatile("mma.sync.aligned.m16n8k16.row.col.f32.f16.f16.f32 "
        "{%0,%1,%2,%3}, {%4,%5,%6,%7}, {%8,%9}, {%0,%1,%2,%3};"
        : "+f"(d[0]), "+f"(d[1]), "+f"(d[2]), "+f"(d[3])
        : "r"(a[0]), "r"(a[1]), "r"(a[2]), "r"(a[3]), "r"(b[0]), "r"(b[1]));
}
__device__ __forceinline__ void cp_async16(uint32_t dst, const void* src) {
    asm volatile("cp.async.cg.shared.global [%0], [%1], 16;" :: "r"(dst), "l"(src));
}
#define CP_COMMIT()  asm volatile("cp.async.commit_group;" ::: "memory")
#define CP_WAIT(n)   asm volatile("cp.async.wait_group %0;" :: "n"(n) : "memory")
#define SWZ(r, gb)   ((uint32_t)((r) * 128 + (((gb)) ^ (((r) & 7) << 4))))

// log2(e) * (1/sqrt(64)) : softmax runs in exp2 domain
#define SCALE_LOG2E 0.18033688f

// ============================================================
// Fused prep kernel: cvt x, cvt mem, transpose W_qkv, transpose+gate W_proj
// ============================================================
#define PREP_X_BLK   (ROWS * CC / 4 / 256)        // 12288
#define PREP_MEM_BLK (MM * CC / 4 / 256)          // 48
#define PREP_WQ_BLK  ((C3/32) * (CC/32))          // 432
#define PREP_WP_BLK  ((CC/32) * (CC/32))          // 144
#define PREP_GRID    (PREP_X_BLK + PREP_MEM_BLK + PREP_WQ_BLK + PREP_WP_BLK)

__global__ __launch_bounds__(256) void prep_kernel(
    const float* __restrict__ x, const float* __restrict__ mem,
    const float* __restrict__ Wq, const float* __restrict__ Wp,
    const float* __restrict__ gate,
    __half* __restrict__ xh, __half* __restrict__ memh,
    __half* __restrict__ wqt, __half* __restrict__ wpt)
{
    __shared__ float t[32][33];
    const int bid = blockIdx.x;
    const int tid = threadIdx.x;

    if (bid < PREP_X_BLK) {
        const int i = bid * 256 + tid;
        float4 v = ((const float4*)x)[i];
        ((__half2*)xh)[i*2+0] = __floats2half2_rn(v.x, v.y);
        ((__half2*)xh)[i*2+1] = __floats2half2_rn(v.z, v.w);
    } else if (bid < PREP_X_BLK + PREP_MEM_BLK) {
        const int i = (bid - PREP_X_BLK) * 256 + tid;
        float4 v = ((const float4*)mem)[i];
        ((__half2*)memh)[i*2+0] = __floats2half2_rn(v.x, v.y);
        ((__half2*)memh)[i*2+1] = __floats2half2_rn(v.z, v.w);
    } else {
        const float* W;
        __half* out;
        int n0, k0, N_;
        bool use_gate;
        if (bid < PREP_X_BLK + PREP_MEM_BLK + PREP_WQ_BLK) {
            const int tb = bid - (PREP_X_BLK + PREP_MEM_BLK);
            W = Wq; out = wqt; N_ = C3; use_gate = false;
            n0 = (tb % (C3/32)) * 32;
            k0 = (tb / (C3/32)) * 32;
        } else {
            const int tb = bid - (PREP_X_BLK + PREP_MEM_BLK + PREP_WQ_BLK);
            W = Wp; out = wpt; N_ = CC; use_gate = true;
            n0 = (tb % (CC/32)) * 32;
            k0 = (tb / (CC/32)) * 32;
        }
        const int tx = tid & 31, ty = tid >> 5;   // 32 x 8
        #pragma unroll
        for (int i = ty; i < 32; i += 8)
            t[i][tx] = W[(size_t)(k0 + i) * N_ + n0 + tx];
        __syncthreads();
        const float g = use_gate ? gate[k0 + tx] : 1.0f;
        #pragma unroll
        for (int i = ty; i < 32; i += 8)
            out[(size_t)(n0 + i) * CC + k0 + tx] = __float2half(t[tx][i] * g);
    }
}

// ============================================================
// fp16 GEMM: C[M,N] = A@B^T + bias ; K = CC = 384, N compile-time.
// CTA 128x128, BK=64, 8 warps (32x64 each), cp.async double-buffer.
// __launch_bounds__(256, 2): cap 128 regs so 2 CTAs/SM are resident
// (R8 ncu: 136 regs -> 1 CTA/SM -> occ 12%, tensor pipe 39%).
// ============================================================
#define BK 64
#define ATILE 16384
#define GEMM_SMEM (4 * 16384)
#define GK CC
#define GNCH (GK / BK)   // 6

template <typename OutT, int N>
__global__ __launch_bounds__(256, 2) void mma_gemm_f16_kernel(
    const __half* __restrict__ A, const __half* __restrict__ B,
    const float* __restrict__ bias, OutT* __restrict__ C)
{
    extern __shared__ __align__(1024) char smem[];
    const uint32_t sb = smem_u32(smem);
    const int tid = threadIdx.x;
    const int wid = tid >> 5, lane = tid & 31;
    const int wm = wid & 3, wn = wid >> 2;
    const int m0 = blockIdx.y * 128, n0 = blockIdx.x * 128;

    uint32_t st_off[4];
    int ld_r[4];
    #pragma unroll
    for (int i = 0; i < 4; ++i) {
        const int u = tid + i * 256;
        const int r = u >> 3, g = u & 7;
        ld_r[i] = r;
        st_off[i] = SWZ(r, g * 16);
    }

    const int arow0 = wm * 32 + (lane & 15);
    const uint32_t a_kx = (uint32_t)((lane >> 4) * 16);
    const int brow0 = wn * 64 + ((lane >> 4) & 1) * 8 + (lane & 7);
    const uint32_t b_kx = (uint32_t)(((lane >> 3) & 1) * 16);

    float acc[2][8][4];
    #pragma unroll
    for (int a = 0; a < 2; ++a)
        #pragma unroll
        for (int b = 0; b < 8; ++b)
            #pragma unroll
            for (int c = 0; c < 4; ++c) acc[a][b][c] = 0.f;

    #pragma unroll
    for (int i = 0; i < 4; ++i) {
        const int r = ld_r[i], g = (tid + i*256) & 7;
        cp_async16(sb + st_off[i],         A + (size_t)(m0 + r) * GK + g * 8);
        cp_async16(sb + ATILE + st_off[i], B + (size_t)(n0 + r) * GK + g * 8);
    }
    CP_COMMIT();

    #pragma unroll
    for (int c = 0; c < GNCH; ++c) {
        const uint32_t buf = (uint32_t)(c & 1) * (2 * ATILE);
        if (c + 1 < GNCH) {
            const int kc = (c + 1) * BK;
            const uint32_t nbuf = (uint32_t)((c + 1) & 1) * (2 * ATILE);
            #pragma unroll
            for (int i = 0; i < 4; ++i) {
                const int r = ld_r[i], g = (tid + i*256) & 7;
                cp_async16(sb + nbuf + st_off[i],         A + (size_t)(m0 + r) * GK + kc + g * 8);
                cp_async16(sb + nbuf + ATILE + st_off[i], B + (size_t)(n0 + r) * GK + kc + g * 8);
            }
            CP_COMMIT();
            CP_WAIT(1);
        } else {
            CP_WAIT(0);
        }
        __syncthreads();

        const uint32_t abase = sb + buf;
        const uint32_t bbase = sb + buf + ATILE;
        #pragma unroll
        for (int ks = 0; ks < 4; ++ks) {
            const uint32_t ksb = (uint32_t)(ks * 32);
            uint32_t af[2][4];
            #pragma unroll
            for (int mt = 0; mt < 2; ++mt) {
                const int r = arow0 + mt * 16;
                ldsm_x4(abase + SWZ(r, ksb + a_kx), af[mt][0], af[mt][1], af[mt][2], af[mt][3]);
            }
            #pragma unroll
            for (int np = 0; np < 4; ++np) {
                uint32_t bf[4];
                const int r = brow0 + np * 16;
                ldsm_x4(bbase + SWZ(r, ksb + b_kx), bf[0], bf[1], bf[2], bf[3]);
                #pragma unroll
                for (int mt = 0; mt < 2; ++mt) {
                    mma_f16(acc[mt][np*2+0], af[mt], &bf[0]);
                    mma_f16(acc[mt][np*2+1], af[mt], &bf[2]);
                }
            }
        }
        __syncthreads();
    }

    #pragma unroll
    for (int mt = 0; mt < 2; ++mt) {
        const int mrow = m0 + wm * 32 + mt * 16 + (lane >> 2);
        #pragma unroll
        for (int nt = 0; nt < 8; ++nt) {
            const int col = n0 + wn * 64 + nt * 8 + (lane & 3) * 2;
            const float b0 = bias[col], b1 = bias[col + 1];
            if (sizeof(OutT) == 2) {
                *(__half2*)&((__half*)C)[(size_t)mrow * N + col] =
                    __floats2half2_rn(acc[mt][nt][0] + b0, acc[mt][nt][1] + b1);
                *(__half2*)&((__half*)C)[(size_t)(mrow + 8) * N + col] =
                    __floats2half2_rn(acc[mt][nt][2] + b0, acc[mt][nt][3] + b1);
            } else {
                *(float2*)&((float*)C)[(size_t)mrow * N + col] =
                    make_float2(acc[mt][nt][0] + b0, acc[mt][nt][1] + b1);
                *(float2*)&((float*)C)[(size_t)(mrow + 8) * N + col] =
                    make_float2(acc[mt][nt][2] + b0, acc[mt][nt][3] + b1);
            }
        }
    }
}

// ============================================================
// Flash-style HMMA attention -> fp16 y.
// Block = (q-tile 64, head, batch), 128 threads = 4 warps.
// Keys 0-127 = memory prefix (V==K there), 128-255 = self window qs-64..qs+63.
// Warp w owns q rows 16w..16w+15. Fully-masked 16-key tiles are skipped:
//   chunk 2 (keys qs-64..qs-1): tile np valid iff np >= w (window)
//   chunk 3 (keys qs..qs+63):   tile np valid iff np <= w (causal)
// Softmax runs in exp2 domain (scale pre-multiplied by log2 e).
// ============================================================
#define QS_OFF 0
#define KS_OFF 8192
#define VS_OFF 40960
#define ATTN_SMEM 57344

__global__ __launch_bounds__(128) void attn_flash_kernel(
    const __half* __restrict__ qkv, const __half* __restrict__ memh,
    __half* __restrict__ y)
{
    extern __shared__ __align__(1024) char smem[];
    const uint32_t sb = smem_u32(smem);
    const int qt = blockIdx.x, h = blockIdx.y, b = blockIdx.z;
    const int qs = qt * 64;
    const int tid = threadIdx.x;
    const int wid = tid >> 5, lane = tid & 31;

    // ---- stage Q (64 rows), K (256 rows), V self (128 rows) ----
    #pragma unroll
    for (int i = 0; i < 4; ++i) {
        const int u = tid + i * 128;
        const int r = u >> 3, g = u & 7;
        cp_async16(sb + QS_OFF + SWZ(r, g * 16),
                   qkv + (size_t)(b*TT + qs + r) * C3 + h*DD + g*8);
    }
    #pragma unroll
    for (int i = 0; i < 16; ++i) {
        const int u = tid + i * 128;
        const int r = u >> 3, g = u & 7;
        if (r < MM) {
            cp_async16(sb + KS_OFF + SWZ(r, g * 16), memh + (size_t)r * CC + h*DD + g*8);
        } else {
            const int p = qs - 64 + (r - MM);
            const int vr = r - MM;
            if (p >= 0) {
                cp_async16(sb + KS_OFF + SWZ(r, g * 16),
                           qkv + (size_t)(b*TT + p) * C3 + CC + h*DD + g*8);
                cp_async16(sb + VS_OFF + SWZ(vr, g * 16),
                           qkv + (size_t)(b*TT + p) * C3 + 2*CC + h*DD + g*8);
            } else {
                const uint4 z = make_uint4(0,0,0,0);
                *(uint4*)(smem + KS_OFF + SWZ(r, g * 16)) = z;
                *(uint4*)(smem + VS_OFF + SWZ(vr, g * 16)) = z;
            }
        }
    }
    CP_COMMIT();
    CP_WAIT(0);
    __syncthreads();

    const int qb = wid * 16;
    const int r_lo = lane >> 2;
    const int c_lo = (lane & 3) * 2;
    const int qi0 = qs + qb + r_lo;
    const int qi1 = qi0 + 8;

    const uint32_t a_kx = (uint32_t)((lane >> 4) * 16);
    const int arow = qb + (lane & 15);
    const int brow_base = ((lane >> 4) & 1) * 8 + (lane & 7);
    const uint32_t b_kx = (uint32_t)(((lane >> 3) & 1) * 16);
    const int vrow_base = ((lane >> 3) & 1) * 8 + (lane & 7);
    const uint32_t v_nx = (uint32_t)((lane >> 4) * 16);

    float O[8][4];
    #pragma unroll
    for (int t = 0; t < 8; ++t)
        #pragma unroll
        for (int e = 0; e < 4; ++e) O[t][e] = 0.f;
    float m0 = -1e30f, m1 = -1e30f, l0 = 0.f, l1 = 0.f;

    #pragma unroll
    for (int c = 0; c < 4; ++c) {
        if (qt == 0 && c == 2) continue;   // self keys p in [-64,-1]: fully masked
        const int kb = c * 64;

        // ---- S = Q K^T (skip fully-masked 16-key tiles) ----
        float s[8][4];
        #pragma unroll
        for (int t = 0; t < 8; ++t)
            #pragma unroll
            for (int e = 0; e < 4; ++e) s[t][e] = 0.f;
        #pragma unroll
        for (int ks = 0; ks < 4; ++ks) {
            const uint32_t ksb = (uint32_t)(ks * 32);
            uint32_t af[4];
            ldsm_x4(sb + QS_OFF + SWZ(arow, ksb + a_kx), af[0], af[1], af[2], af[3]);
            #pragma unroll
            for (int np = 0; np < 4; ++np) {
                if (c == 2 && np < wid) continue;
                if (c == 3 && np > wid) continue;
                uint32_t bf[4];
                const int r = kb + np * 16 + brow_base;
                ldsm_x4(sb + KS_OFF + SWZ(r, ksb + b_kx), bf[0], bf[1], bf[2], bf[3]);
                mma_f16(s[np*2+0], af, &bf[0]);
                mma_f16(s[np*2+1], af, &bf[2]);
            }
        }

        // ---- scale (exp2 domain) + mask ----
        #pragma unroll
        for (int t = 0; t < 8; ++t) {
            #pragma unroll
            for (int e = 0; e < 4; ++e) {
                const int key = kb + t*8 + c_lo + (e & 1);
                const int qi = (e < 2) ? qi0 : qi1;
                bool valid = true;
                if (key >= MM) {
                    const int p = qs - 64 + (key - MM);
                    valid = (p >= 0) && (p <= qi) && (qi - p <= WIN);
                }
                s[t][e] = valid ? s[t][e] * SCALE_LOG2E : -1e30f;
            }
        }

        // ---- online softmax (exp2 domain) ----
        float cm0 = -1e30f, cm1 = -1e30f;
        #pragma unroll
        for (int t = 0; t < 8; ++t) {
            cm0 = fmaxf(cm0, fmaxf(s[t][0], s[t][1]));
            cm1 = fmaxf(cm1, fmaxf(s[t][2], s[t][3]));
        }
        cm0 = fmaxf(cm0, __shfl_xor_sync(0xFFFFFFFFu, cm0, 1));
        cm0 = fmaxf(cm0, __shfl_xor_sync(0xFFFFFFFFu, cm0, 2));
        cm1 = fmaxf(cm1, __shfl_xor_sync(0xFFFFFFFFu, cm1, 1));
        cm1 = fmaxf(cm1, __shfl_xor_sync(0xFFFFFFFFu, cm1, 2));
        const float mn0 = fmaxf(m0, cm0), mn1 = fmaxf(m1, cm1);
        const float sc0 = exp2f(m0 - mn0), sc1 = exp2f(m1 - mn1);
        m0 = mn0; m1 = mn1;
        l0 *= sc0; l1 *= sc1;
        #pragma unroll
        for (int t = 0; t < 8; ++t) {
            O[t][0] *= sc0; O[t][1] *= sc0;
            O[t][2] *= sc1; O[t][3] *= sc1;
        }
        uint32_t ph[8][2];
        #pragma unroll
        for (int t = 0; t < 8; ++t) {
            const float p0 = exp2f(s[t][0] - mn0), p1 = exp2f(s[t][1] - mn0);
            const float p2 = exp2f(s[t][2] - mn1), p3 = exp2f(s[t][3] - mn1);
            l0 += p0 + p1; l1 += p2 + p3;
            __half2 h01 = __floats2half2_rn(p0, p1);
            __half2 h23 = __floats2half2_rn(p2, p3);
            ph[t][0] = *(uint32_t*)&h01;
            ph[t][1] = *(uint32_t*)&h23;
        }

        // ---- O += P V (mem prefix V rows live in K buffer; skip masked tiles) ----
        #pragma unroll
        for (int ks = 0; ks < 4; ++ks) {
            if (c == 2 && ks < wid) continue;
            if (c == 3 && ks > wid) continue;
            uint32_t a[4] = { ph[2*ks][0], ph[2*ks][1], ph[2*ks+1][0], ph[2*ks+1][1] };
            const int rv = kb + ks * 16 + vrow_base;
            #pragma unroll
            for (int g = 0; g < 4; ++g) {
                uint32_t vb[4];
                uint32_t addr;
                if (kb < MM)
                    addr = sb + KS_OFF + SWZ(rv, (uint32_t)(g * 32) + v_nx);
                else
                    addr = sb + VS_OFF + SWZ(rv - MM, (uint32_t)(g * 32) + v_nx);
                ldsm_x4t(addr, vb[0], vb[1], vb[2], vb[3]);
                mma_f16(O[g*2+0], a, &vb[0]);
                mma_f16(O[g*2+1], a, &vb[2]);
            }
        }
    }

    // ---- finalize: write fp16 y ----
    l0 += __shfl_xor_sync(0xFFFFFFFFu, l0, 1);
    l0 += __shfl_xor_sync(0xFFFFFFFFu, l0, 2);
    l1 += __shfl_xor_sync(0xFFFFFFFFu, l1, 1);
    l1 += __shfl_xor_sync(0xFFFFFFFFu, l1, 2);
    const float rc0 = 1.0f / l0, rc1 = 1.0f / l1;

    const size_t row0 = (size_t)(b*TT + qs + qb + r_lo);
    #pragma unroll
    for (int t = 0; t < 8; ++t) {
        const int col = h*DD + t*8 + c_lo;
        *(__half2*)&y[row0 * CC + col] =
            __floats2half2_rn(O[t][0] * rc0, O[t][1] * rc0);
        *(__half2*)&y[(row0 + 8) * CC + col] =
            __floats2half2_rn(O[t][2] * rc1, O[t][3] * rc1);
    }
}

// ============================================================
extern "C" void kernel_launch(void* const* d_in, const int* in_sizes, int n_in,
                              void* d_out, int out_size)
{
    const float* x      = (const float*)d_in[0];
    const float* mem    = (const float*)d_in[1];
    const float* W_qkv  = (const float*)d_in[2];
    const float* b_qkv  = (const float*)d_in[3];
    const float* W_proj = (const float*)d_in[4];
    const float* b_proj = (const float*)d_in[5];
    const float* gate   = (const float*)d_in[6];
    float* out = (float*)d_out;

    void *pqh, *pyh, *pxh, *pwqh, *pwph, *pmh;
    cudaGetSymbolAddress(&pqh, g_qkv_h);
    cudaGetSymbolAddress(&pyh, g_yh);
    cudaGetSymbolAddress(&pxh, g_xh);
    cudaGetSymbolAddress(&pwqh, g_wqt_h);
    cudaGetSymbolAddress(&pwph, g_wpt_h);
    cudaGetSymbolAddress(&pmh, g_mem_h);

    cudaFuncSetAttribute((const void*)mma_gemm_f16_kernel<__half, C3>,
        cudaFuncAttributeMaxDynamicSharedMemorySize, GEMM_SMEM);
    cudaFuncSetAttribute((const void*)mma_gemm_f16_kernel<float, CC>,
        cudaFuncAttributeMaxDynamicSharedMemorySize, GEMM_SMEM);
    cudaFuncSetAttribute((const void*)attn_flash_kernel,
        cudaFuncAttributeMaxDynamicSharedMemorySize, ATTN_SMEM);

    // fused prep: cvt x, cvt mem, transpose W_qkv, transpose+gate W_proj
    prep_kernel<<<PREP_GRID, 256>>>(x, mem, W_qkv, W_proj, gate,
        (__half*)pxh, (__half*)pmh, (__half*)pwqh, (__half*)pwph);

    // QKV = x @ W_qkv + b_qkv (fp16 -> fp16)
    mma_gemm_f16_kernel<__half, C3><<<dim3(C3/128, ROWS/128), 256, GEMM_SMEM>>>(
        (const __half*)pxh, (const __half*)pwqh, b_qkv, (__half*)pqh);

    // attention -> y fp16 (pre-gate)
    attn_flash_kernel<<<dim3(TT/64, HH, BB), 128, ATTN_SMEM>>>(
        (const __half*)pqh, (const __half*)pmh, (__half*)pyh);

    // out = y @ (gate.W_proj) + b_proj (fp16 -> fp32)
    mma_gemm_f16_kernel<float, CC><<<dim3(CC/128, ROWS/128), 256, GEMM_SMEM>>>(
        (const __half*)pyh, (const __half*)pwph, b_proj, out);
}

// round 12
// speedup vs baseline: 9.3294x; 1.0087x over previous
#include <cuda_runtime.h>
#include <cuda_bf16.h>
#include <cuda_fp16.h>
#include <cstdint>

// Problem constants
#define BB   128
#define TT   256
#define CC   384
#define HH   6
#define DD   64
#define MM   128
#define WIN  64
#define C3   (3*CC)      // 1152
#define ROWS (BB*TT)     // 32768

// Scratch (allocation-free rule: __device__ globals)
__device__ __half g_qkv_h[ROWS * C3];   // fp16 qkv
__device__ __half g_yh[ROWS * CC];      // attention output fp16 (pre-gate)
__device__ __half g_xh[ROWS * CC];      // x fp16
__device__ __half g_wqt_h[C3 * CC];     // W_qkv^T fp16 [1152,384]
__device__ __half g_wpt_h[CC * CC];     // (diag(gate) W_proj)^T fp16 [384,384]
__device__ __half g_mem_h[MM * CC];     // memory fp16

// ---------- mma helpers (generic sm_80+ path; compiles on .target sm_103) ----------
__device__ __forceinline__ uint32_t smem_u32(const void* p) {
    uint32_t a;
    asm("{ .reg .u64 t; cvta.to.shared.u64 t, %1; cvt.u32.u64 %0, t; }" : "=r"(a) : "l"(p));
    return a;
}
__device__ __forceinline__ void ldsm_x4(uint32_t addr, uint32_t& r0, uint32_t& r1,
                                        uint32_t& r2, uint32_t& r3) {
    asm volatile("ldmatrix.sync.aligned.m8n8.x4.shared.b16 {%0,%1,%2,%3}, [%4];"
        : "=r"(r0), "=r"(r1), "=r"(r2), "=r"(r3) : "r"(addr));
}
__device__ __forceinline__ void ldsm_x4t(uint32_t addr, uint32_t& r0, uint32_t& r1,
                                         uint32_t& r2, uint32_t& r3) {
    asm volatile("ldmatrix.sync.aligned.m8n8.x4.trans.shared.b16 {%0,%1,%2,%3}, [%4];"
        : "=r"(r0), "=r"(r1), "=r"(r2), "=r"(r3) : "r"(addr));
}
__device__ __forceinline__ void mma_f16(float* d, const uint32_t* a, const uint32_t* b) {
    asm volatile("mma.sync.aligned.m16n8k16.row.col.f32.f16.f16.f32 "
        "{%0,%1,%2,%3}, {%4,%5,%6,%7}, {%8,%9}, {%0,%1,%2,%3};"
        : "+f"(d[0]), "+f"(d[1]), "+f"(d[2]), "+f"(d[3])
        : "r"(a[0]), "r"(a[1]), "r"(a[2]), "r"(a[3]), "r"(b[0]), "r"(b[1]));
}
__device__ __forceinline__ void cp_async16(uint32_t dst, const void* src) {
    asm volatile("cp.async.cg.shared.global [%0], [%1], 16;" :: "r"(dst), "l"(src));
}
#define CP_COMMIT()  asm volatile("cp.async.commit_group;" ::: "memory")
#define CP_WAIT(n)   asm volatile("cp.async.wait_group %0;" :: "n"(n) : "memory")
#define SWZ(r, gb)   ((uint32_t)((r) * 128 + (((gb)) ^ (((r) & 7) << 4))))

// log2(e) * (1/sqrt(64)) : softmax runs in exp2 domain
#define SCALE_LOG2E 0.18033688f

// ============================================================
// Fused prep kernel: cvt x, cvt mem, transpose W_qkv, transpose+gate W_proj
// ============================================================
#define PREP_X_BLK   (ROWS * CC / 4 / 256)        // 12288
#define PREP_MEM_BLK (MM * CC / 4 / 256)          // 48
#define PREP_WQ_BLK  ((C3/32) * (CC/32))          // 432
#define PREP_WP_BLK  ((CC/32) * (CC/32))          // 144
#define PREP_GRID    (PREP_X_BLK + PREP_MEM_BLK + PREP_WQ_BLK + PREP_WP_BLK)

__global__ __launch_bounds__(256) void prep_kernel(
    const float* __restrict__ x, const float* __restrict__ mem,
    const float* __restrict__ Wq, const float* __restrict__ Wp,
    const float* __restrict__ gate,
    __half* __restrict__ xh, __half* __restrict__ memh,
    __half* __restrict__ wqt, __half* __restrict__ wpt)
{
    __shared__ float t[32][33];
    const int bid = blockIdx.x;
    const int tid = threadIdx.x;

    if (bid < PREP_X_BLK) {
        const int i = bid * 256 + tid;
        float4 v = ((const float4*)x)[i];
        ((__half2*)xh)[i*2+0] = __floats2half2_rn(v.x, v.y);
        ((__half2*)xh)[i*2+1] = __floats2half2_rn(v.z, v.w);
    } else if (bid < PREP_X_BLK + PREP_MEM_BLK) {
        const int i = (bid - PREP_X_BLK) * 256 + tid;
        float4 v = ((const float4*)mem)[i];
        ((__half2*)memh)[i*2+0] = __floats2half2_rn(v.x, v.y);
        ((__half2*)memh)[i*2+1] = __floats2half2_rn(v.z, v.w);
    } else {
        const float* W;
        __half* out;
        int n0, k0, N_;
        bool use_gate;
        if (bid < PREP_X_BLK + PREP_MEM_BLK + PREP_WQ_BLK) {
            const int tb = bid - (PREP_X_BLK + PREP_MEM_BLK);
            W = Wq; out = wqt; N_ = C3; use_gate = false;
            n0 = (tb % (C3/32)) * 32;
            k0 = (tb / (C3/32)) * 32;
        } else {
            const int tb = bid - (PREP_X_BLK + PREP_MEM_BLK + PREP_WQ_BLK);
            W = Wp; out = wpt; N_ = CC; use_gate = true;
            n0 = (tb % (CC/32)) * 32;
            k0 = (tb / (CC/32)) * 32;
        }
        const int tx = tid & 31, ty = tid >> 5;   // 32 x 8
        #pragma unroll
        for (int i = ty; i < 32; i += 8)
            t[i][tx] = W[(size_t)(k0 + i) * N_ + n0 + tx];
        __syncthreads();
        const float g = use_gate ? gate[k0 + tx] : 1.0f;
        #pragma unroll
        for (int i = ty; i < 32; i += 8)
            out[(size_t)(n0 + i) * CC + k0 + tx] = __float2half(t[tx][i] * g);
    }
}

// ============================================================
// fp16 GEMM: C[M,N] = A@B^T + bias ; K = CC = 384, N compile-time.
// CTA 128x128, BK=64, 8 warps (32x64 each).
// 3-stage cp.async pipeline, ONE __syncthreads per K-chunk:
//   top-of-iter barrier proves all warps finished chunk c-1's ldsm,
//   so prefetching stage (c+2)%3 (== (c-1)%3) after it is race-free.
// __launch_bounds__(256, 2): 128 regs, 2 CTAs/SM (96KB smem x2 fits).
// ============================================================
#define BK 64
#define ATILE 16384
#define STAGE_BYTES (2 * ATILE)        // 32 KB per stage (A+B)
#define GEMM_SMEM (3 * STAGE_BYTES)    // 96 KB
#define GK CC
#define GNCH (GK / BK)   // 6

__device__ __forceinline__ void gemm_prefetch(
    uint32_t dst_base, const __half* __restrict__ A, const __half* __restrict__ B,
    int m0, int n0, int kc, const uint32_t* st_off, const int* ld_r, int tid)
{
    #pragma unroll
    for (int i = 0; i < 4; ++i) {
        const int r = ld_r[i], g = (tid + i * 256) & 7;
        cp_async16(dst_base + st_off[i],         A + (size_t)(m0 + r) * GK + kc + g * 8);
        cp_async16(dst_base + ATILE + st_off[i], B + (size_t)(n0 + r) * GK + kc + g * 8);
    }
    CP_COMMIT();
}

template <typename OutT, int N>
__global__ __launch_bounds__(256, 2) void mma_gemm_f16_kernel(
    const __half* __restrict__ A, const __half* __restrict__ B,
    const float* __restrict__ bias, OutT* __restrict__ C)
{
    extern __shared__ __align__(1024) char smem[];
    const uint32_t sb = smem_u32(smem);
    const int tid = threadIdx.x;
    const int wid = tid >> 5, lane = tid & 31;
    const int wm = wid & 3, wn = wid >> 2;
    const int m0 = blockIdx.y * 128, n0 = blockIdx.x * 128;

    uint32_t st_off[4];
    int ld_r[4];
    #pragma unroll
    for (int i = 0; i < 4; ++i) {
        const int u = tid + i * 256;
        const int r = u >> 3, g = u & 7;
        ld_r[i] = r;
        st_off[i] = SWZ(r, g * 16);
    }

    const int arow0 = wm * 32 + (lane & 15);
    const uint32_t a_kx = (uint32_t)((lane >> 4) * 16);
    const int brow0 = wn * 64 + ((lane >> 4) & 1) * 8 + (lane & 7);
    const uint32_t b_kx = (uint32_t)(((lane >> 3) & 1) * 16);

    float acc[2][8][4];
    #pragma unroll
    for (int a = 0; a < 2; ++a)
        #pragma unroll
        for (int b = 0; b < 8; ++b)
            #pragma unroll
            for (int c = 0; c < 4; ++c) acc[a][b][c] = 0.f;

    // prologue: stages 0 and 1 in flight
    gemm_prefetch(sb + 0 * STAGE_BYTES, A, B, m0, n0, 0 * BK, st_off, ld_r, tid);
    gemm_prefetch(sb + 1 * STAGE_BYTES, A, B, m0, n0, 1 * BK, st_off, ld_r, tid);

    #pragma unroll
    for (int c = 0; c < GNCH; ++c) {
        if (c == GNCH - 1) { CP_WAIT(0); } else { CP_WAIT(1); }   // chunk c resident
        __syncthreads();    // all warps done reading stage (c+2)%3 (iter c-1) + see chunk c
        if (c + 2 < GNCH)
            gemm_prefetch(sb + ((c + 2) % 3) * STAGE_BYTES, A, B, m0, n0,
                          (c + 2) * BK, st_off, ld_r, tid);

        const uint32_t abase = sb + (c % 3) * STAGE_BYTES;
        const uint32_t bbase = abase + ATILE;
        #pragma unroll
        for (int ks = 0; ks < 4; ++ks) {
            const uint32_t ksb = (uint32_t)(ks * 32);
            uint32_t af[2][4];
            #pragma unroll
            for (int mt = 0; mt < 2; ++mt) {
                const int r = arow0 + mt * 16;
                ldsm_x4(abase + SWZ(r, ksb + a_kx), af[mt][0], af[mt][1], af[mt][2], af[mt][3]);
            }
            #pragma unroll
            for (int np = 0; np < 4; ++np) {
                uint32_t bf[4];
                const int r = brow0 + np * 16;
                ldsm_x4(bbase + SWZ(r, ksb + b_kx), bf[0], bf[1], bf[2], bf[3]);
                #pragma unroll
                for (int mt = 0; mt < 2; ++mt) {
                    mma_f16(acc[mt][np*2+0], af[mt], &bf[0]);
                    mma_f16(acc[mt][np*2+1], af[mt], &bf[2]);
                }
            }
        }
    }

    #pragma unroll
    for (int mt = 0; mt < 2; ++mt) {
        const int mrow = m0 + wm * 32 + mt * 16 + (lane >> 2);
        #pragma unroll
        for (int nt = 0; nt < 8; ++nt) {
            const int col = n0 + wn * 64 + nt * 8 + (lane & 3) * 2;
            const float b0 = bias[col], b1 = bias[col + 1];
            if (sizeof(OutT) == 2) {
                *(__half2*)&((__half*)C)[(size_t)mrow * N + col] =
                    __floats2half2_rn(acc[mt][nt][0] + b0, acc[mt][nt][1] + b1);
                *(__half2*)&((__half*)C)[(size_t)(mrow + 8) * N + col] =
                    __floats2half2_rn(acc[mt][nt][2] + b0, acc[mt][nt][3] + b1);
            } else {
                *(float2*)&((float*)C)[(size_t)mrow * N + col] =
                    make_float2(acc[mt][nt][0] + b0, acc[mt][nt][1] + b1);
                *(float2*)&((float*)C)[(size_t)(mrow + 8) * N + col] =
                    make_float2(acc[mt][nt][2] + b0, acc[mt][nt][3] + b1);
            }
        }
    }
}

// ============================================================
// Flash-style HMMA attention -> fp16 y.
// Block = (q-tile 64, head, batch), 128 threads = 4 warps.
// Keys 0-127 = memory prefix (V==K there), 128-255 = self window qs-64..qs+63.
// Warp w owns q rows 16w..16w+15. Fully-masked 16-key tiles are skipped:
//   chunk 2 (keys qs-64..qs-1): tile np valid iff np >= w (window)
//   chunk 3 (keys qs..qs+63):   tile np valid iff np <= w (causal)
// Softmax runs in exp2 domain (scale pre-multiplied by log2 e).
// ============================================================
#define QS_OFF 0
#define KS_OFF 8192
#define VS_OFF 40960
#define ATTN_SMEM 57344

__global__ __launch_bounds__(128) void attn_flash_kernel(
    const __half* __restrict__ qkv, const __half* __restrict__ memh,
    __half* __restrict__ y)
{
    extern __shared__ __align__(1024) char smem[];
    const uint32_t sb = smem_u32(smem);
    const int qt = blockIdx.x, h = blockIdx.y, b = blockIdx.z;
    const int qs = qt * 64;
    const int tid = threadIdx.x;
    const int wid = tid >> 5, lane = tid & 31;

    // ---- stage Q (64 rows), K (256 rows), V self (128 rows) ----
    #pragma unroll
    for (int i = 0; i < 4; ++i) {
        const int u = tid + i * 128;
        const int r = u >> 3, g = u & 7;
        cp_async16(sb + QS_OFF + SWZ(r, g * 16),
                   qkv + (size_t)(b*TT + qs + r) * C3 + h*DD + g*8);
    }
    #pragma unroll
    for (int i = 0; i < 16; ++i) {
        const int u = tid + i * 128;
        const int r = u >> 3, g = u & 7;
        if (r < MM) {
            cp_async16(sb + KS_OFF + SWZ(r, g * 16), memh + (size_t)r * CC + h*DD + g*8);
        } else {
            const int p = qs - 64 + (r - MM);
            const int vr = r - MM;
            if (p >= 0) {
                cp_async16(sb + KS_OFF + SWZ(r, g * 16),
                           qkv + (size_t)(b*TT + p) * C3 + CC + h*DD + g*8);
                cp_async16(sb + VS_OFF + SWZ(vr, g * 16),
                           qkv + (size_t)(b*TT + p) * C3 + 2*CC + h*DD + g*8);
            } else {
                const uint4 z = make_uint4(0,0,0,0);
                *(uint4*)(smem + KS_OFF + SWZ(r, g * 16)) = z;
                *(uint4*)(smem + VS_OFF + SWZ(vr, g * 16)) = z;
            }
        }
    }
    CP_COMMIT();
    CP_WAIT(0);
    __syncthreads();

    const int qb = wid * 16;
    const int r_lo = lane >> 2;
    const int c_lo = (lane & 3) * 2;
    const int qi0 = qs + qb + r_lo;
    const int qi1 = qi0 + 8;

    const uint32_t a_kx = (uint32_t)((lane >> 4) * 16);
    const int arow = qb + (lane & 15);
    const int brow_base = ((lane >> 4) & 1) * 8 + (lane & 7);
    const uint32_t b_kx = (uint32_t)(((lane >> 3) & 1) * 16);
    const int vrow_base = ((lane >> 3) & 1) * 8 + (lane & 7);
    const uint32_t v_nx = (uint32_t)((lane >> 4) * 16);

    float O[8][4];
    #pragma unroll
    for (int t = 0; t < 8; ++t)
        #pragma unroll
        for (int e = 0; e < 4; ++e) O[t][e] = 0.f;
    float m0 = -1e30f, m1 = -1e30f, l0 = 0.f, l1 = 0.f;

    #pragma unroll
    for (int c = 0; c < 4; ++c) {
        if (qt == 0 && c == 2) continue;   // self keys p in [-64,-1]: fully masked
        const int kb = c * 64;

        // ---- S = Q K^T (skip fully-masked 16-key tiles) ----
        float s[8][4];
        #pragma unroll
        for (int t = 0; t < 8; ++t)
            #pragma unroll
            for (int e = 0; e < 4; ++e) s[t][e] = 0.f;
        #pragma unroll
        for (int ks = 0; ks < 4; ++ks) {
            const uint32_t ksb = (uint32_t)(ks * 32);
            uint32_t af[4];
            ldsm_x4(sb + QS_OFF + SWZ(arow, ksb + a_kx), af[0], af[1], af[2], af[3]);
            #pragma unroll
            for (int np = 0; np < 4; ++np) {
                if (c == 2 && np < wid) continue;
                if (c == 3 && np > wid) continue;
                uint32_t bf[4];
                const int r = kb + np * 16 + brow_base;
                ldsm_x4(sb + KS_OFF + SWZ(r, ksb + b_kx), bf[0], bf[1], bf[2], bf[3]);
                mma_f16(s[np*2+0], af, &bf[0]);
                mma_f16(s[np*2+1], af, &bf[2]);
            }
        }

        // ---- scale (exp2 domain) + mask ----
        #pragma unroll
        for (int t = 0; t < 8; ++t) {
            #pragma unroll
            for (int e = 0; e < 4; ++e) {
                const int key = kb + t*8 + c_lo + (e & 1);
                const int qi = (e < 2) ? qi0 : qi1;
                bool valid = true;
                if (key >= MM) {
                    const int p = qs - 64 + (key - MM);
                    valid = (p >= 0) && (p <= qi) && (qi - p <= WIN);
                }
                s[t][e] = valid ? s[t][e] * SCALE_LOG2E : -1e30f;
            }
        }

        // ---- online softmax (exp2 domain) ----
        float cm0 = -1e30f, cm1 = -1e30f;
        #pragma unroll
        for (int t = 0; t < 8; ++t) {
            cm0 = fmaxf(cm0, fmaxf(s[t][0], s[t][1]));
            cm1 = fmaxf(cm1, fmaxf(s[t][2], s[t][3]));
        }
        cm0 = fmaxf(cm0, __shfl_xor_sync(0xFFFFFFFFu, cm0, 1));
        cm0 = fmaxf(cm0, __shfl_xor_sync(0xFFFFFFFFu, cm0, 2));
        cm1 = fmaxf(cm1, __shfl_xor_sync(0xFFFFFFFFu, cm1, 1));
        cm1 = fmaxf(cm1, __shfl_xor_sync(0xFFFFFFFFu, cm1, 2));
        const float mn0 = fmaxf(m0, cm0), mn1 = fmaxf(m1, cm1);
        const float sc0 = exp2f(m0 - mn0), sc1 = exp2f(m1 - mn1);
        m0 = mn0; m1 = mn1;
        l0 *= sc0; l1 *= sc1;
        #pragma unroll
        for (int t = 0; t < 8; ++t) {
            O[t][0] *= sc0; O[t][1] *= sc0;
            O[t][2] *= sc1; O[t][3] *= sc1;
        }
        uint32_t ph[8][2];
        #pragma unroll
        for (int t = 0; t < 8; ++t) {
            const float p0 = exp2f(s[t][0] - mn0), p1 = exp2f(s[t][1] - mn0);
            const float p2 = exp2f(s[t][2] - mn1), p3 = exp2f(s[t][3] - mn1);
            l0 += p0 + p1; l1 += p2 + p3;
            __half2 h01 = __floats2half2_rn(p0, p1);
            __half2 h23 = __floats2half2_rn(p2, p3);
            ph[t][0] = *(uint32_t*)&h01;
            ph[t][1] = *(uint32_t*)&h23;
        }

        // ---- O += P V (mem prefix V rows live in K buffer; skip masked tiles) ----
        #pragma unroll
        for (int ks = 0; ks < 4; ++ks) {
            if (c == 2 && ks < wid) continue;
            if (c == 3 && ks > wid) continue;
            uint32_t a[4] = { ph[2*ks][0], ph[2*ks][1], ph[2*ks+1][0], ph[2*ks+1][1] };
            const int rv = kb + ks * 16 + vrow_base;
            #pragma unroll
            for (int g = 0; g < 4; ++g) {
                uint32_t vb[4];
                uint32_t addr;
                if (kb < MM)
                    addr = sb + KS_OFF + SWZ(rv, (uint32_t)(g * 32) + v_nx);
                else
                    addr = sb + VS_OFF + SWZ(rv - MM, (uint32_t)(g * 32) + v_nx);
                ldsm_x4t(addr, vb[0], vb[1], vb[2], vb[3]);
                mma_f16(O[g*2+0], a, &vb[0]);
                mma_f16(O[g*2+1], a, &vb[2]);
            }
        }
    }

    // ---- finalize: write fp16 y ----
    l0 += __shfl_xor_sync(0xFFFFFFFFu, l0, 1);
    l0 += __shfl_xor_sync(0xFFFFFFFFu, l0, 2);
    l1 += __shfl_xor_sync(0xFFFFFFFFu, l1, 1);
    l1 += __shfl_xor_sync(0xFFFFFFFFu, l1, 2);
    const float rc0 = 1.0f / l0, rc1 = 1.0f / l1;

    const size_t row0 = (size_t)(b*TT + qs + qb + r_lo);
    #pragma unroll
    for (int t = 0; t < 8; ++t) {
        const int col = h*DD + t*8 + c_lo;
        *(__half2*)&y[row0 * CC + col] =
            __floats2half2_rn(O[t][0] * rc0, O[t][1] * rc0);
        *(__half2*)&y[(row0 + 8) * CC + col] =
            __floats2half2_rn(O[t][2] * rc1, O[t][3] * rc1);
    }
}

// ============================================================
extern "C" void kernel_launch(void* const* d_in, const int* in_sizes, int n_in,
                              void* d_out, int out_size)
{
    const float* x      = (const float*)d_in[0];
    const float* mem    = (const float*)d_in[1];
    const float* W_qkv  = (const float*)d_in[2];
    const float* b_qkv  = (const float*)d_in[3];
    const float* W_proj = (const float*)d_in[4];
    const float* b_proj = (const float*)d_in[5];
    const float* gate   = (const float*)d_in[6];
    float* out = (float*)d_out;

    void *pqh, *pyh, *pxh, *pwqh, *pwph, *pmh;
    cudaGetSymbolAddress(&pqh, g_qkv_h);
    cudaGetSymbolAddress(&pyh, g_yh);
    cudaGetSymbolAddress(&pxh, g_xh);
    cudaGetSymbolAddress(&pwqh, g_wqt_h);
    cudaGetSymbolAddress(&pwph, g_wpt_h);
    cudaGetSymbolAddress(&pmh, g_mem_h);

    cudaFuncSetAttribute((const void*)mma_gemm_f16_kernel<__half, C3>,
        cudaFuncAttributeMaxDynamicSharedMemorySize, GEMM_SMEM);
    cudaFuncSetAttribute((const void*)mma_gemm_f16_kernel<float, CC>,
        cudaFuncAttributeMaxDynamicSharedMemorySize, GEMM_SMEM);
    cudaFuncSetAttribute((const void*)attn_flash_kernel,
        cudaFuncAttributeMaxDynamicSharedMemorySize, ATTN_SMEM);

    // fused prep: cvt x, cvt mem, transpose W_qkv, transpose+gate W_proj
    prep_kernel<<<PREP_GRID, 256>>>(x, mem, W_qkv, W_proj, gate,
        (__half*)pxh, (__half*)pmh, (__half*)pwqh, (__half*)pwph);

    // QKV = x @ W_qkv + b_qkv (fp16 -> fp16)
    mma_gemm_f16_kernel<__half, C3><<<dim3(C3/128, ROWS/128), 256, GEMM_SMEM>>>(
        (const __half*)pxh, (const __half*)pwqh, b_qkv, (__half*)pqh);

    // attention -> y fp16 (pre-gate)
    attn_flash_kernel<<<dim3(TT/64, HH, BB), 128, ATTN_SMEM>>>(
        (const __half*)pqh, (const __half*)pmh, (__half*)pyh);

    // out = y @ (gate.W_proj) + b_proj (fp16 -> fp32)
    mma_gemm_f16_kernel<float, CC><<<dim3(CC/128, ROWS/128), 256, GEMM_SMEM>>>(
        (const __half*)pyh, (const __half*)pwph, b_proj, out);
}